// round 1
// baseline (speedup 1.0000x reference)
#include <cuda_runtime.h>
#include <math.h>

// Problem constants
// B=8, S=128, H=768, M=128, P = S(S+1)/2 = 8256
#define Bn 8
#define Sn 128
#define Hn 768
#define Mn 128
#define Pn 8256

// Scratch (allocation-free rule: __device__ globals)
__device__ float g_xhat[Bn*Sn*Hn];          // 3 MB : (x-mean)/(var+eps)^2
__device__ float g_gc  [Bn*Sn*Hn];          // 3 MB : seq @ w_gamma^T + gamma
__device__ float g_bc  [Bn*Sn*Hn];          // 3 MB : seq @ w_beta^T  + beta
__device__ float g_Cmat[3*Bn*Sn*Mn];        // 1.5MB: bc @ W_k + bias_k

// ---------------------------------------------------------------------------
// Kernel 1: per-row mean/var, write xhat = (x-mean) / (var+eps)^2
// NOTE: reference does std = (var+eps)**2  (squared, NOT sqrt) — replicate.
// ---------------------------------------------------------------------------
__global__ void __launch_bounds__(256) stats_kernel(const float* __restrict__ seq) {
    __shared__ float warp_s[8];
    __shared__ float stat[2];
    const int r   = blockIdx.x;            // 0..1023  (b*128+s)
    const int tid = threadIdx.x;
    const float* x = seq + (size_t)r * Hn;
    float v0 = x[tid], v1 = x[tid + 256], v2 = x[tid + 512];

    // mean
    float s = v0 + v1 + v2;
    #pragma unroll
    for (int o = 16; o; o >>= 1) s += __shfl_xor_sync(0xffffffffu, s, o);
    if ((tid & 31) == 0) warp_s[tid >> 5] = s;
    __syncthreads();
    if (tid == 0) {
        float t = 0.f;
        #pragma unroll
        for (int i = 0; i < 8; i++) t += warp_s[i];
        stat[0] = t * (1.0f / (float)Hn);
    }
    __syncthreads();
    const float mean = stat[0];
    float d0 = v0 - mean, d1 = v1 - mean, d2 = v2 - mean;

    // var
    float s2 = d0*d0 + d1*d1 + d2*d2;
    #pragma unroll
    for (int o = 16; o; o >>= 1) s2 += __shfl_xor_sync(0xffffffffu, s2, o);
    if ((tid & 31) == 0) warp_s[tid >> 5] = s2;
    __syncthreads();
    if (tid == 0) {
        float t = 0.f;
        #pragma unroll
        for (int i = 0; i < 8; i++) t += warp_s[i];
        float var = t * (1.0f / (float)Hn);
        float d = var + 1e-12f;
        stat[1] = 1.0f / (d * d);          // reference: out / (var+eps)^2
    }
    __syncthreads();
    const float inv = stat[1];
    float* xo = g_xhat + (size_t)r * Hn;
    xo[tid]       = d0 * inv;
    xo[tid + 256] = d1 * inv;
    xo[tid + 512] = d2 * inv;
}

// ---------------------------------------------------------------------------
// Kernel 2: NT GEMM  C[r,o] = sum_h seq[r,h] * W[o,h] + bias[o]
//   rows 1024, cols 768, K 768.  z=0 -> (w_gamma,gamma)->g_gc ; z=1 -> g_bc
//   Tiles 128x128x16, 256 threads, 8x8 micro-tile (strided: ty+16u / tx+16v).
// ---------------------------------------------------------------------------
__global__ void __launch_bounds__(256) cln_gemm_kernel(
    const float* __restrict__ seq,
    const float* __restrict__ w_gamma, const float* __restrict__ gamma,
    const float* __restrict__ w_beta,  const float* __restrict__ beta)
{
    __shared__ float Ash[16][132];
    __shared__ float Wsh[16][132];
    const int z = blockIdx.z;
    const float* W    = z ? w_beta : w_gamma;
    const float* bias = z ? beta   : gamma;
    float* dst        = z ? g_bc   : g_gc;
    const int r0 = blockIdx.x * 128;
    const int c0 = blockIdx.y * 128;
    const int tid = threadIdx.x;
    const int tx = tid & 15, ty = tid >> 4;
    const int lr = tid >> 1, half = tid & 1, kb = half * 8;

    float acc[8][8];
    #pragma unroll
    for (int u = 0; u < 8; u++)
        #pragma unroll
        for (int v = 0; v < 8; v++) acc[u][v] = 0.f;

    for (int k0 = 0; k0 < Hn; k0 += 16) {
        const float4* ap = (const float4*)(seq + (size_t)(r0 + lr) * Hn + k0 + kb);
        float4 a0 = ap[0], a1 = ap[1];
        const float4* wp = (const float4*)(W + (size_t)(c0 + lr) * Hn + k0 + kb);
        float4 w0 = wp[0], w1 = wp[1];
        Ash[kb+0][lr] = a0.x; Ash[kb+1][lr] = a0.y; Ash[kb+2][lr] = a0.z; Ash[kb+3][lr] = a0.w;
        Ash[kb+4][lr] = a1.x; Ash[kb+5][lr] = a1.y; Ash[kb+6][lr] = a1.z; Ash[kb+7][lr] = a1.w;
        Wsh[kb+0][lr] = w0.x; Wsh[kb+1][lr] = w0.y; Wsh[kb+2][lr] = w0.z; Wsh[kb+3][lr] = w0.w;
        Wsh[kb+4][lr] = w1.x; Wsh[kb+5][lr] = w1.y; Wsh[kb+6][lr] = w1.z; Wsh[kb+7][lr] = w1.w;
        __syncthreads();
        #pragma unroll
        for (int kk = 0; kk < 16; kk++) {
            float a[8], w[8];
            #pragma unroll
            for (int u = 0; u < 8; u++) a[u] = Ash[kk][ty + 16*u];
            #pragma unroll
            for (int v = 0; v < 8; v++) w[v] = Wsh[kk][tx + 16*v];
            #pragma unroll
            for (int u = 0; u < 8; u++)
                #pragma unroll
                for (int v = 0; v < 8; v++) acc[u][v] += a[u] * w[v];
        }
        __syncthreads();
    }
    #pragma unroll
    for (int u = 0; u < 8; u++) {
        int rr = r0 + ty + 16*u;
        #pragma unroll
        for (int v = 0; v < 8; v++) {
            int cc = c0 + tx + 16*v;
            dst[(size_t)rr * Hn + cc] = acc[u][v] + bias[cc];
        }
    }
}

// ---------------------------------------------------------------------------
// Kernel 3: NN GEMM  Cmat[k][r][m] = sum_h bc[r,h] * Wk[h,m] + bias_k[m]
//   rows 1024, cols 128, K 768.  grid (8, 3)
// ---------------------------------------------------------------------------
__global__ void __launch_bounds__(256) cmat_gemm_kernel(
    const float* __restrict__ w_ent,  const float* __restrict__ b_ent,
    const float* __restrict__ w_head, const float* __restrict__ b_head,
    const float* __restrict__ w_tail, const float* __restrict__ b_tail)
{
    __shared__ float Ash[16][132];
    __shared__ float Bsh[16][132];
    const int k = blockIdx.y;
    const float* W    = (k == 0) ? w_ent : (k == 1) ? w_head : w_tail;
    const float* bias = (k == 0) ? b_ent : (k == 1) ? b_head : b_tail;
    const int r0 = blockIdx.x * 128;
    const int tid = threadIdx.x;
    const int tx = tid & 15, ty = tid >> 4;
    const int lr = tid >> 1, half = tid & 1, kb = half * 8;
    const int lkk = tid >> 4, lm0 = (tid & 15) * 8;

    float acc[8][8];
    #pragma unroll
    for (int u = 0; u < 8; u++)
        #pragma unroll
        for (int v = 0; v < 8; v++) acc[u][v] = 0.f;

    for (int k0 = 0; k0 < Hn; k0 += 16) {
        const float4* ap = (const float4*)(g_bc + (size_t)(r0 + lr) * Hn + k0 + kb);
        float4 a0 = ap[0], a1 = ap[1];
        const float4* bp = (const float4*)(W + (size_t)(k0 + lkk) * Mn + lm0);
        float4 b0 = bp[0], b1 = bp[1];
        Ash[kb+0][lr] = a0.x; Ash[kb+1][lr] = a0.y; Ash[kb+2][lr] = a0.z; Ash[kb+3][lr] = a0.w;
        Ash[kb+4][lr] = a1.x; Ash[kb+5][lr] = a1.y; Ash[kb+6][lr] = a1.z; Ash[kb+7][lr] = a1.w;
        *(float4*)&Bsh[lkk][lm0]     = b0;
        *(float4*)&Bsh[lkk][lm0 + 4] = b1;
        __syncthreads();
        #pragma unroll
        for (int kk = 0; kk < 16; kk++) {
            float a[8], w[8];
            #pragma unroll
            for (int u = 0; u < 8; u++) a[u] = Ash[kk][ty + 16*u];
            #pragma unroll
            for (int v = 0; v < 8; v++) w[v] = Bsh[kk][tx + 16*v];
            #pragma unroll
            for (int u = 0; u < 8; u++)
                #pragma unroll
                for (int v = 0; v < 8; v++) acc[u][v] += a[u] * w[v];
        }
        __syncthreads();
    }
    #pragma unroll
    for (int u = 0; u < 8; u++) {
        int rr = r0 + ty + 16*u;
        #pragma unroll
        for (int v = 0; v < 8; v++) {
            int cc = tx + 16*v;
            g_Cmat[((size_t)k * (Bn*Sn) + rr) * Mn + cc] = acc[u][v] + bias[cc];
        }
    }
}

// ---------------------------------------------------------------------------
// Kernel 4: fused per-pair GEMM + tanh epilogue.
//   Block = (b, i, head k). Rows j in [j0, 128), j0 = ibase (32-aligned).
//   A[j,h] = xhat[b,j,h] * gc[b,i,h]  (built in the smem A-tile load)
//   out[k][b][p(i,j)][m] = tanh(acc + Cmat[k][b*128+i][m]),  p = off(i)+j-i
//   UR = rows/16 template cuts triangular waste (2.0x -> 1.25x).
// ---------------------------------------------------------------------------
template<int UR>
__global__ void __launch_bounds__(256) fused_pair_kernel(
    float* __restrict__ out,
    const float* __restrict__ w_ent,
    const float* __restrict__ w_head,
    const float* __restrict__ w_tail,
    int ibase)
{
    __shared__ float Ash[16][132];
    __shared__ float Bsh[16][132];
    __shared__ float gcs[Hn];
    __shared__ float Ssh[16][136];

    const int i = ibase + (blockIdx.x & 31);
    const int b = blockIdx.x >> 5;
    const int k = blockIdx.y;
    const float* W = (k == 0) ? w_ent : (k == 1) ? w_head : w_tail;

    const int j0 = ibase;                // rows j in [j0, 128)
    const int rows = UR * 16;
    const int tid = threadIdx.x;
    const int tx = tid & 15, ty = tid >> 4;
    const int lr = tid >> 1, half = tid & 1, kb = half * 8;
    const int lkk = tid >> 4, lm0 = (tid & 15) * 8;

    // cache the conditioning gamma row
    const float* gcrow = g_gc + (size_t)(b * Sn + i) * Hn;
    for (int h = tid; h < Hn; h += 256) gcs[h] = gcrow[h];
    __syncthreads();

    float acc[UR][8];
    #pragma unroll
    for (int u = 0; u < UR; u++)
        #pragma unroll
        for (int v = 0; v < 8; v++) acc[u][v] = 0.f;

    const float* xbase = g_xhat + (size_t)(b * Sn + j0) * Hn;

    for (int k0 = 0; k0 < Hn; k0 += 16) {
        if (lr < rows) {
            const float4* ap = (const float4*)(xbase + (size_t)lr * Hn + k0 + kb);
            float4 a0 = ap[0], a1 = ap[1];
            float4 gA = *(const float4*)&gcs[k0 + kb];
            float4 gB = *(const float4*)&gcs[k0 + kb + 4];
            Ash[kb+0][lr] = a0.x * gA.x; Ash[kb+1][lr] = a0.y * gA.y;
            Ash[kb+2][lr] = a0.z * gA.z; Ash[kb+3][lr] = a0.w * gA.w;
            Ash[kb+4][lr] = a1.x * gB.x; Ash[kb+5][lr] = a1.y * gB.y;
            Ash[kb+6][lr] = a1.z * gB.z; Ash[kb+7][lr] = a1.w * gB.w;
        }
        const float4* bp = (const float4*)(W + (size_t)(k0 + lkk) * Mn + lm0);
        float4 b0 = bp[0], b1 = bp[1];
        *(float4*)&Bsh[lkk][lm0]     = b0;
        *(float4*)&Bsh[lkk][lm0 + 4] = b1;
        __syncthreads();
        #pragma unroll
        for (int kk = 0; kk < 16; kk++) {
            float a[UR], w[8];
            #pragma unroll
            for (int u = 0; u < UR; u++) a[u] = Ash[kk][ty + 16*u];
            #pragma unroll
            for (int v = 0; v < 8; v++) w[v] = Bsh[kk][tx + 16*v];
            #pragma unroll
            for (int u = 0; u < UR; u++)
                #pragma unroll
                for (int v = 0; v < 8; v++) acc[u][v] += a[u] * w[v];
        }
        __syncthreads();
    }

    // epilogue: + Cmat, tanh, stage through smem for coalesced float4 stores
    float Cc[8];
    const float* crow = g_Cmat + ((size_t)k * (Bn*Sn) + b * Sn + i) * Mn;
    #pragma unroll
    for (int v = 0; v < 8; v++) Cc[v] = crow[tx + 16*v];

    const int offi = i * Sn - (i * (i - 1)) / 2;        // triu pair offset
    const size_t base = ((size_t)(k * Bn + b) * Pn + (size_t)(offi - i)) * Mn;

    #pragma unroll
    for (int u = 0; u < UR; u++) {
        #pragma unroll
        for (int v = 0; v < 8; v++)
            Ssh[ty][tx + 16*v] = tanhf(acc[u][v] + Cc[v]);
        __syncthreads();
        const int rr = tid >> 4;
        const int mm = (tid & 15) * 8;
        const int j  = j0 + u * 16 + rr;
        if (j >= i) {
            float* dp = out + base + (size_t)j * Mn + mm;
            *(float4*)dp       = *(const float4*)&Ssh[rr][mm];
            *(float4*)(dp + 4) = *(const float4*)&Ssh[rr][mm + 4];
        }
        __syncthreads();
    }
}

// ---------------------------------------------------------------------------
extern "C" void kernel_launch(void* const* d_in, const int* in_sizes, int n_in,
                              void* d_out, int out_size) {
    (void)in_sizes; (void)n_in; (void)out_size;
    const float* seq     = (const float*)d_in[0];
    const float* gamma   = (const float*)d_in[1];
    const float* beta    = (const float*)d_in[2];
    const float* w_beta  = (const float*)d_in[3];
    const float* w_gamma = (const float*)d_in[4];
    const float* w_ent   = (const float*)d_in[5];
    const float* b_ent   = (const float*)d_in[6];
    const float* w_head  = (const float*)d_in[7];
    const float* b_head  = (const float*)d_in[8];
    const float* w_tail  = (const float*)d_in[9];
    const float* b_tail  = (const float*)d_in[10];
    float* out = (float*)d_out;

    stats_kernel<<<Bn * Sn, 256>>>(seq);
    cln_gemm_kernel<<<dim3(8, 6, 2), 256>>>(seq, w_gamma, gamma, w_beta, beta);
    cmat_gemm_kernel<<<dim3(8, 3), 256>>>(w_ent, b_ent, w_head, b_head, w_tail, b_tail);

    fused_pair_kernel<8><<<dim3(256, 3), 256>>>(out, w_ent, w_head, w_tail, 0);
    fused_pair_kernel<6><<<dim3(256, 3), 256>>>(out, w_ent, w_head, w_tail, 32);
    fused_pair_kernel<4><<<dim3(256, 3), 256>>>(out, w_ent, w_head, w_tail, 64);
    fused_pair_kernel<2><<<dim3(256, 3), 256>>>(out, w_ent, w_head, w_tail, 96);
}

// round 3
// speedup vs baseline: 1.8143x; 1.8143x over previous
#include <cuda_runtime.h>
#include <cuda_bf16.h>
#include <math.h>
#include <stdint.h>

// Problem constants: B=8, S=128, H=768, M=128, P = S(S+1)/2 = 8256
#define Bn 8
#define Sn 128
#define Hn 768
#define Mn 128
#define Pn 8256

// Scratch (__device__ globals; allocation-free rule)
__device__ float g_xhat[Bn*Sn*Hn];                        // (x-mean)/(var+eps)^2
__device__ float g_gc  [Bn*Sn*Hn];                        // seq @ w_gamma^T + gamma
__device__ float g_bc  [Bn*Sn*Hn];                        // seq @ w_beta^T  + beta
__device__ float g_Cmat[3*Bn*Sn*Mn];                      // bc @ W_k + bias_k
__device__ __align__(16) __nv_bfloat16 g_Wt_hi[3*Mn*Hn];  // W_k^T hi  [k][m][h]
__device__ __align__(16) __nv_bfloat16 g_Wt_lo[3*Mn*Hn];  // W_k^T lo

// ---------------------------------------------------------------------------
__device__ __forceinline__ uint32_t smem_u32(const void* p) {
    uint32_t a;
    asm("{ .reg .u64 t; cvta.to.shared.u64 t, %1; cvt.u32.u64 %0, t; }" : "=r"(a) : "l"(p));
    return a;
}
__device__ __forceinline__ uint32_t lds32(uint32_t a) {
    uint32_t v;
    asm volatile("ld.shared.b32 %0, [%1];" : "=r"(v) : "r"(a));
    return v;
}
__device__ __forceinline__ void mma16816(float& d0, float& d1, float& d2, float& d3,
                                         uint32_t a0, uint32_t a1, uint32_t a2, uint32_t a3,
                                         uint32_t b0, uint32_t b1) {
    asm volatile(
        "mma.sync.aligned.m16n8k16.row.col.f32.bf16.bf16.f32 "
        "{%0,%1,%2,%3},{%4,%5,%6,%7},{%8,%9},{%0,%1,%2,%3};"
        : "+f"(d0), "+f"(d1), "+f"(d2), "+f"(d3)
        : "r"(a0), "r"(a1), "r"(a2), "r"(a3), "r"(b0), "r"(b1));
}
#define CP16(dst, src) \
    asm volatile("cp.async.cg.shared.global [%0], [%1], 16;" :: "r"(dst), "l"(src) : "memory")
#define CP_COMMIT() asm volatile("cp.async.commit_group;" ::: "memory")
#define CP_WAIT0()  asm volatile("cp.async.wait_group 0;" ::: "memory")

__device__ __forceinline__ float tanh_fast(float x) {
    float ax = fabsf(x);
    float e  = __expf(2.0f * ax);
    float r  = 1.0f - 2.0f / (e + 1.0f);
    return copysignf(r, x);
}

// ===========================================================================
// Kernel 1: per-row mean/var, xhat = (x-mean)/(var+eps)^2  (ref quirk: squared)
// ===========================================================================
__global__ void __launch_bounds__(256) stats_kernel(const float* __restrict__ seq) {
    __shared__ float warp_s[8];
    __shared__ float stat[2];
    const int r   = blockIdx.x;
    const int tid = threadIdx.x;
    const float* x = seq + (size_t)r * Hn;
    float v0 = x[tid], v1 = x[tid + 256], v2 = x[tid + 512];
    float s = v0 + v1 + v2;
    #pragma unroll
    for (int o = 16; o; o >>= 1) s += __shfl_xor_sync(0xffffffffu, s, o);
    if ((tid & 31) == 0) warp_s[tid >> 5] = s;
    __syncthreads();
    if (tid == 0) {
        float t = 0.f;
        #pragma unroll
        for (int i = 0; i < 8; i++) t += warp_s[i];
        stat[0] = t * (1.0f / (float)Hn);
    }
    __syncthreads();
    const float mean = stat[0];
    float d0 = v0 - mean, d1 = v1 - mean, d2 = v2 - mean;
    float s2 = d0*d0 + d1*d1 + d2*d2;
    #pragma unroll
    for (int o = 16; o; o >>= 1) s2 += __shfl_xor_sync(0xffffffffu, s2, o);
    if ((tid & 31) == 0) warp_s[tid >> 5] = s2;
    __syncthreads();
    if (tid == 0) {
        float t = 0.f;
        #pragma unroll
        for (int i = 0; i < 8; i++) t += warp_s[i];
        float var = t * (1.0f / (float)Hn);
        float d = var + 1e-12f;
        stat[1] = 1.0f / (d * d);
    }
    __syncthreads();
    const float inv = stat[1];
    float* xo = g_xhat + (size_t)r * Hn;
    xo[tid]       = d0 * inv;
    xo[tid + 256] = d1 * inv;
    xo[tid + 512] = d2 * inv;
}

// ===========================================================================
// Kernel 2: NT GEMM -> g_gc / g_bc  (1024 x 768, K=768)
// ===========================================================================
__global__ void __launch_bounds__(256) cln_gemm_kernel(
    const float* __restrict__ seq,
    const float* __restrict__ w_gamma, const float* __restrict__ gamma,
    const float* __restrict__ w_beta,  const float* __restrict__ beta)
{
    __shared__ float Ash[16][132];
    __shared__ float Wsh[16][132];
    const int z = blockIdx.z;
    const float* W    = z ? w_beta : w_gamma;
    const float* bias = z ? beta   : gamma;
    float* dst        = z ? g_bc   : g_gc;
    const int r0 = blockIdx.x * 128;
    const int c0 = blockIdx.y * 128;
    const int tid = threadIdx.x;
    const int tx = tid & 15, ty = tid >> 4;
    const int lr = tid >> 1, kb = (tid & 1) * 8;

    float acc[8][8];
    #pragma unroll
    for (int u = 0; u < 8; u++)
        #pragma unroll
        for (int v = 0; v < 8; v++) acc[u][v] = 0.f;

    for (int k0 = 0; k0 < Hn; k0 += 16) {
        const float4* ap = (const float4*)(seq + (size_t)(r0 + lr) * Hn + k0 + kb);
        float4 a0 = ap[0], a1 = ap[1];
        const float4* wp = (const float4*)(W + (size_t)(c0 + lr) * Hn + k0 + kb);
        float4 w0 = wp[0], w1 = wp[1];
        Ash[kb+0][lr] = a0.x; Ash[kb+1][lr] = a0.y; Ash[kb+2][lr] = a0.z; Ash[kb+3][lr] = a0.w;
        Ash[kb+4][lr] = a1.x; Ash[kb+5][lr] = a1.y; Ash[kb+6][lr] = a1.z; Ash[kb+7][lr] = a1.w;
        Wsh[kb+0][lr] = w0.x; Wsh[kb+1][lr] = w0.y; Wsh[kb+2][lr] = w0.z; Wsh[kb+3][lr] = w0.w;
        Wsh[kb+4][lr] = w1.x; Wsh[kb+5][lr] = w1.y; Wsh[kb+6][lr] = w1.z; Wsh[kb+7][lr] = w1.w;
        __syncthreads();
        #pragma unroll
        for (int kk = 0; kk < 16; kk++) {
            float a[8], w[8];
            #pragma unroll
            for (int u = 0; u < 8; u++) a[u] = Ash[kk][ty + 16*u];
            #pragma unroll
            for (int v = 0; v < 8; v++) w[v] = Wsh[kk][tx + 16*v];
            #pragma unroll
            for (int u = 0; u < 8; u++)
                #pragma unroll
                for (int v = 0; v < 8; v++) acc[u][v] += a[u] * w[v];
        }
        __syncthreads();
    }
    #pragma unroll
    for (int u = 0; u < 8; u++) {
        int rr = r0 + ty + 16*u;
        #pragma unroll
        for (int v = 0; v < 8; v++) {
            int cc = c0 + tx + 16*v;
            dst[(size_t)rr * Hn + cc] = acc[u][v] + bias[cc];
        }
    }
}

// ===========================================================================
// Kernel 3: NN GEMM -> g_Cmat[k][r][m] = bc[r,:] @ Wk + bias_k
// ===========================================================================
__global__ void __launch_bounds__(256) cmat_gemm_kernel(
    const float* __restrict__ w_ent,  const float* __restrict__ b_ent,
    const float* __restrict__ w_head, const float* __restrict__ b_head,
    const float* __restrict__ w_tail, const float* __restrict__ b_tail)
{
    __shared__ float Ash[16][132];
    __shared__ float Bsh[16][132];
    const int k = blockIdx.y;
    const float* W    = (k == 0) ? w_ent : (k == 1) ? w_head : w_tail;
    const float* bias = (k == 0) ? b_ent : (k == 1) ? b_head : b_tail;
    const int r0 = blockIdx.x * 128;
    const int tid = threadIdx.x;
    const int tx = tid & 15, ty = tid >> 4;
    const int lr = tid >> 1, kb = (tid & 1) * 8;
    const int lkk = tid >> 4, lm0 = (tid & 15) * 8;

    float acc[8][8];
    #pragma unroll
    for (int u = 0; u < 8; u++)
        #pragma unroll
        for (int v = 0; v < 8; v++) acc[u][v] = 0.f;

    for (int k0 = 0; k0 < Hn; k0 += 16) {
        const float4* ap = (const float4*)(g_bc + (size_t)(r0 + lr) * Hn + k0 + kb);
        float4 a0 = ap[0], a1 = ap[1];
        const float4* bp = (const float4*)(W + (size_t)(k0 + lkk) * Mn + lm0);
        float4 b0 = bp[0], b1 = bp[1];
        Ash[kb+0][lr] = a0.x; Ash[kb+1][lr] = a0.y; Ash[kb+2][lr] = a0.z; Ash[kb+3][lr] = a0.w;
        Ash[kb+4][lr] = a1.x; Ash[kb+5][lr] = a1.y; Ash[kb+6][lr] = a1.z; Ash[kb+7][lr] = a1.w;
        *(float4*)&Bsh[lkk][lm0]     = b0;
        *(float4*)&Bsh[lkk][lm0 + 4] = b1;
        __syncthreads();
        #pragma unroll
        for (int kk = 0; kk < 16; kk++) {
            float a[8], w[8];
            #pragma unroll
            for (int u = 0; u < 8; u++) a[u] = Ash[kk][ty + 16*u];
            #pragma unroll
            for (int v = 0; v < 8; v++) w[v] = Bsh[kk][tx + 16*v];
            #pragma unroll
            for (int u = 0; u < 8; u++)
                #pragma unroll
                for (int v = 0; v < 8; v++) acc[u][v] += a[u] * w[v];
        }
        __syncthreads();
    }
    #pragma unroll
    for (int u = 0; u < 8; u++) {
        int rr = r0 + ty + 16*u;
        #pragma unroll
        for (int v = 0; v < 8; v++) {
            int cc = tx + 16*v;
            g_Cmat[((size_t)k * (Bn*Sn) + rr) * Mn + cc] = acc[u][v] + bias[cc];
        }
    }
}

// ===========================================================================
// Kernel 3b: transpose+split projection weights -> g_Wt_hi/lo [k][m][h] bf16
// ===========================================================================
__global__ void __launch_bounds__(256) wsplit_kernel(
    const float* __restrict__ w_ent,
    const float* __restrict__ w_head,
    const float* __restrict__ w_tail)
{
    int idx = blockIdx.x * 256 + threadIdx.x;
    if (idx >= 3 * Mn * Hn) return;
    int k  = idx / (Mn * Hn);
    int rm = idx - k * (Mn * Hn);
    int m  = rm / Hn;
    int h  = rm - m * Hn;
    const float* W = (k == 0) ? w_ent : (k == 1) ? w_head : w_tail;
    float v = W[(size_t)h * Mn + m];
    __nv_bfloat16 hi = __float2bfloat16(v);
    float lo = v - __bfloat162float(hi);
    g_Wt_hi[idx] = hi;
    g_Wt_lo[idx] = __float2bfloat16(lo);
}

// ===========================================================================
// Kernel 4: mma.sync (HMMA) bf16x3 pair GEMM + fused tanh epilogue.
//   One CTA per (b,i). 256 thr = 8 warps, warp grid 4(m) x 2(n).
//   D[j=0..127][n=0..383] (3 heads x 128), K=768 in 24 chunks of 32.
//   A[j,h] = xhat[b,j,h]*gc[b,i,h], split hi(truncate)/lo per chunk, once
//   for all 3 heads. 3 passes: Ah*Wh + Ah*Wl + Al*Wh (fp32 acc).
//   Smem rows stride 80B -> conflict-free fragment LDS.
//   Double-buffered: W via cp.async, A built into alt stage during compute.
// ===========================================================================
#define KC 32
#define NCH 24                    // 768/32
#define RSTRIDE 80                // 64B data + 16B pad (bank-disjoint frags)
#define A_TB   (128 * RSTRIDE)    // 10240 per (stage,hl)
#define W_TB   (384 * RSTRIDE)    // 30720 per (stage,hl)
#define OFF_A  0                  // [stage][hl] : 2*2*10240 = 40960
#define OFF_W  40960              // [stage][hl] : 2*2*30720 = 122880
#define OFF_GC 163840             // 768 f32
#define OFF_CM 166912             // 384 f32
#define SMEM_DYN (168448 + 128)

__global__ void __launch_bounds__(256, 1) pair_mma_kernel(float* __restrict__ out) {
    extern __shared__ __align__(128) char dsm[];
    const uint32_t sB = smem_u32(dsm);
    float* gcs   = (float*)(dsm + OFF_GC);
    float* cmatS = (float*)(dsm + OFF_CM);

    const int tid  = threadIdx.x;
    const int wid  = tid >> 5;
    const int lane = tid & 31;
    const int g    = lane >> 2;
    const int tg   = lane & 3;
    const int wm   = wid >> 1;          // 0..3 : rows wm*32
    const int wn   = wid & 1;           // 0..1 : cols wn*64 (within 384? no: per-head 128; see below)
    const int i = blockIdx.x & 127;
    const int b = blockIdx.x >> 7;

    // stage conditioning row + bias rows
    {
        const float* gsrc = g_gc + (size_t)(b * Sn + i) * Hn;
        for (int t = tid; t < Hn; t += 256) gcs[t] = gsrc[t];
        for (int t = tid; t < 384; t += 256)
            cmatS[t] = g_Cmat[((size_t)(t >> 7) * (Bn*Sn) + b * Sn + i) * Mn + (t & 127)];
    }
    __syncthreads();

    float acc[3][2][8][4];
    #pragma unroll
    for (int h = 0; h < 3; h++)
        #pragma unroll
        for (int mt = 0; mt < 2; mt++)
            #pragma unroll
            for (int nt = 0; nt < 8; nt++)
                #pragma unroll
                for (int r = 0; r < 4; r++) acc[h][mt][nt][r] = 0.f;

    // fill lambda-ish: build A(hi/lo) + cp.async W for chunk c into stage s
    const int frow  = tid >> 1;         // 0..127
    const int fhalf = tid & 1;          // 16-element half of the 32-chunk
    const float* xrow = g_xhat + (size_t)(b * Sn + frow) * Hn;

    #define FILL(c, s) do {                                                        \
        const int kc = (c) * KC;                                                   \
        /* ---- A build: 16 products, truncation split ---- */                     \
        const float4* xp = (const float4*)(xrow + kc + fhalf * 16);                \
        const float4* gp = (const float4*)(gcs + kc + fhalf * 16);                 \
        uint32_t hiP[8], loP[8];                                                   \
        _Pragma("unroll")                                                          \
        for (int q = 0; q < 4; q++) {                                              \
            float4 xv = xp[q], gv = gp[q];                                         \
            float p0 = xv.x * gv.x, p1 = xv.y * gv.y;                              \
            float p2 = xv.z * gv.z, p3 = xv.w * gv.w;                              \
            uint32_t h01 = __byte_perm(__float_as_uint(p0), __float_as_uint(p1), 0x7632); \
            uint32_t h23 = __byte_perm(__float_as_uint(p2), __float_as_uint(p3), 0x7632); \
            float r0 = p0 - __uint_as_float(__float_as_uint(p0) & 0xffff0000u);    \
            float r1 = p1 - __uint_as_float(__float_as_uint(p1) & 0xffff0000u);    \
            float r2 = p2 - __uint_as_float(__float_as_uint(p2) & 0xffff0000u);    \
            float r3 = p3 - __uint_as_float(__float_as_uint(p3) & 0xffff0000u);    \
            __nv_bfloat162 l01 = __floats2bfloat162_rn(r0, r1);                    \
            __nv_bfloat162 l23 = __floats2bfloat162_rn(r2, r3);                    \
            hiP[2*q] = h01; hiP[2*q+1] = h23;                                      \
            loP[2*q] = *(uint32_t*)&l01; loP[2*q+1] = *(uint32_t*)&l23;            \
        }                                                                          \
        {                                                                          \
            char* ab = dsm + OFF_A + (s) * (2*A_TB);                               \
            uint32_t ro = frow * RSTRIDE + fhalf * 32;                             \
            *(uint4*)(ab + ro)          = *(uint4*)&hiP[0];                        \
            *(uint4*)(ab + ro + 16)     = *(uint4*)&hiP[4];                        \
            *(uint4*)(ab + A_TB + ro)      = *(uint4*)&loP[0];                     \
            *(uint4*)(ab + A_TB + ro + 16) = *(uint4*)&loP[4];                     \
        }                                                                          \
        /* ---- W: cp.async 3 heads x hi/lo, 32B per (thread,head,hl) ---- */      \
        {                                                                          \
            uint32_t wb = sB + OFF_W + (s) * (2*W_TB);                             \
            uint32_t ro = frow * RSTRIDE + fhalf * 32;                             \
            _Pragma("unroll")                                                      \
            for (int h = 0; h < 3; h++) {                                          \
                size_t src = (size_t)(h * Mn + frow) * Hn + kc + fhalf * 16;       \
                uint32_t d0 = wb + h * (128 * RSTRIDE) + ro;                       \
                CP16(d0,          (const char*)(g_Wt_hi + src));                   \
                CP16(d0 + 16,     (const char*)(g_Wt_hi + src + 8));               \
                CP16(d0 + W_TB,      (const char*)(g_Wt_lo + src));                \
                CP16(d0 + W_TB + 16, (const char*)(g_Wt_lo + src + 8));            \
            }                                                                      \
        }                                                                          \
        CP_COMMIT();                                                               \
    } while (0)

    FILL(0, 0);

    const uint32_t aRowBase = (uint32_t)((wm * 32 + g) * RSTRIDE);
    const uint32_t wColBase = (uint32_t)((wn * 64 + g) * RSTRIDE);

    for (int c = 0; c < NCH; ++c) {
        const int s = c & 1;
        CP_WAIT0();
        __syncthreads();
        if (c + 1 < NCH) FILL(c + 1, s ^ 1);

        const uint32_t aH = sB + OFF_A + s * (2*A_TB);
        const uint32_t aL = aH + A_TB;
        const uint32_t wH = sB + OFF_W + s * (2*W_TB);
        const uint32_t wL = wH + W_TB;

        #pragma unroll
        for (int ks = 0; ks < 2; ks++) {
            const uint32_t ko = ks * 32 + tg * 4;
            uint32_t Ah[2][4], Al[2][4];
            #pragma unroll
            for (int mt = 0; mt < 2; mt++) {
                uint32_t base = aRowBase + mt * (16 * RSTRIDE) + ko;
                Ah[mt][0] = lds32(aH + base);
                Ah[mt][1] = lds32(aH + base + 8 * RSTRIDE);
                Ah[mt][2] = lds32(aH + base + 16);
                Ah[mt][3] = lds32(aH + base + 8 * RSTRIDE + 16);
                Al[mt][0] = lds32(aL + base);
                Al[mt][1] = lds32(aL + base + 8 * RSTRIDE);
                Al[mt][2] = lds32(aL + base + 16);
                Al[mt][3] = lds32(aL + base + 8 * RSTRIDE + 16);
            }
            #pragma unroll
            for (int h = 0; h < 3; h++) {
                #pragma unroll
                for (int nt = 0; nt < 8; nt++) {
                    uint32_t wb = wColBase + (h * 128 + nt * 8) * RSTRIDE + ko;
                    uint32_t Bh0 = lds32(wH + wb);
                    uint32_t Bh1 = lds32(wH + wb + 16);
                    uint32_t Bl0 = lds32(wL + wb);
                    uint32_t Bl1 = lds32(wL + wb + 16);
                    #pragma unroll
                    for (int mt = 0; mt < 2; mt++) {
                        float* d = acc[h][mt][nt];
                        mma16816(d[0], d[1], d[2], d[3],
                                 Ah[mt][0], Ah[mt][1], Ah[mt][2], Ah[mt][3], Bh0, Bh1);
                        mma16816(d[0], d[1], d[2], d[3],
                                 Ah[mt][0], Ah[mt][1], Ah[mt][2], Ah[mt][3], Bl0, Bl1);
                        mma16816(d[0], d[1], d[2], d[3],
                                 Al[mt][0], Al[mt][1], Al[mt][2], Al[mt][3], Bh0, Bh1);
                    }
                }
            }
        }
        __syncthreads();
    }

    // ---- epilogue: + Cmat bias, tanh, masked stores ----
    const int offi = i * Sn - (i * (i - 1)) / 2;
    #pragma unroll
    for (int h = 0; h < 3; h++) {
        const size_t hb = (size_t)(h * Bn + b) * Pn;
        #pragma unroll
        for (int mt = 0; mt < 2; mt++) {
            const int j0 = wm * 32 + mt * 16 + g;
            #pragma unroll
            for (int nt = 0; nt < 8; nt++) {
                const int m = wn * 64 + nt * 8 + tg * 2;
                const float cm0 = cmatS[h * 128 + m];
                const float cm1 = cmatS[h * 128 + m + 1];
                const float* d = acc[h][mt][nt];
                if (j0 >= i) {
                    float2 v0 = make_float2(tanh_fast(d[0] + cm0), tanh_fast(d[1] + cm1));
                    *(float2*)(out + (hb + (size_t)(offi - i + j0)) * Mn + m) = v0;
                }
                const int j1 = j0 + 8;
                if (j1 >= i) {
                    float2 v1 = make_float2(tanh_fast(d[2] + cm0), tanh_fast(d[3] + cm1));
                    *(float2*)(out + (hb + (size_t)(offi - i + j1)) * Mn + m) = v1;
                }
            }
        }
    }
}

// ===========================================================================
extern "C" void kernel_launch(void* const* d_in, const int* in_sizes, int n_in,
                              void* d_out, int out_size) {
    (void)in_sizes; (void)n_in; (void)out_size;
    const float* seq     = (const float*)d_in[0];
    const float* gamma   = (const float*)d_in[1];
    const float* beta    = (const float*)d_in[2];
    const float* w_beta  = (const float*)d_in[3];
    const float* w_gamma = (const float*)d_in[4];
    const float* w_ent   = (const float*)d_in[5];
    const float* b_ent   = (const float*)d_in[6];
    const float* w_head  = (const float*)d_in[7];
    const float* b_head  = (const float*)d_in[8];
    const float* w_tail  = (const float*)d_in[9];
    const float* b_tail  = (const float*)d_in[10];
    float* out = (float*)d_out;

    static int attr_set = 0;
    cudaFuncSetAttribute(pair_mma_kernel,
                         cudaFuncAttributeMaxDynamicSharedMemorySize, SMEM_DYN);
    (void)attr_set;

    stats_kernel<<<Bn * Sn, 256>>>(seq);
    cln_gemm_kernel<<<dim3(8, 6, 2), 256>>>(seq, w_gamma, gamma, w_beta, beta);
    wsplit_kernel<<<(3 * Mn * Hn + 255) / 256, 256>>>(w_ent, w_head, w_tail);
    cmat_gemm_kernel<<<dim3(8, 3), 256>>>(w_ent, b_ent, w_head, b_head, w_tail, b_tail);
    pair_mma_kernel<<<Bn * Sn, 256, SMEM_DYN>>>(out);
}

// round 5
// speedup vs baseline: 2.2707x; 1.2516x over previous
#include <cuda_runtime.h>
#include <cuda_bf16.h>
#include <math.h>
#include <stdint.h>

// Problem constants: B=8, S=128, H=768, M=128, P = S(S+1)/2 = 8256
#define Bn 8
#define Sn 128
#define Hn 768
#define Mn 128
#define Pn 8256

// Scratch (__device__ globals; allocation-free rule)
__device__ float g_xhat[Bn*Sn*Hn];                        // (x-mean)/(var+eps)^2
__device__ float g_gc  [Bn*Sn*Hn];                        // seq @ w_gamma^T + gamma
__device__ float g_bc  [Bn*Sn*Hn];                        // seq @ w_beta^T  + beta
__device__ float g_Cmat[3*Bn*Sn*Mn];                      // bc @ W_k + bias_k
__device__ __align__(16) __nv_bfloat16 g_Wt_hi[3*Mn*Hn];  // W_k^T hi  [k][m][h]
__device__ __align__(16) __nv_bfloat16 g_Wt_lo[3*Mn*Hn];  // W_k^T lo

// ---------------------------------------------------------------------------
__device__ __forceinline__ uint32_t smem_u32(const void* p) {
    uint32_t a;
    asm("{ .reg .u64 t; cvta.to.shared.u64 t, %1; cvt.u32.u64 %0, t; }" : "=r"(a) : "l"(p));
    return a;
}
__device__ __forceinline__ uint32_t lds32(uint32_t a) {
    uint32_t v;
    asm volatile("ld.shared.b32 %0, [%1];" : "=r"(v) : "r"(a));
    return v;
}
__device__ __forceinline__ void mma16816(float& d0, float& d1, float& d2, float& d3,
                                         uint32_t a0, uint32_t a1, uint32_t a2, uint32_t a3,
                                         uint32_t b0, uint32_t b1) {
    asm volatile(
        "mma.sync.aligned.m16n8k16.row.col.f32.bf16.bf16.f32 "
        "{%0,%1,%2,%3},{%4,%5,%6,%7},{%8,%9},{%0,%1,%2,%3};"
        : "+f"(d0), "+f"(d1), "+f"(d2), "+f"(d3)
        : "r"(a0), "r"(a1), "r"(a2), "r"(a3), "r"(b0), "r"(b1));
}
#define CP16(dst, src) \
    asm volatile("cp.async.cg.shared.global [%0], [%1], 16;" :: "r"(dst), "l"(src) : "memory")
#define CP_COMMIT() asm volatile("cp.async.commit_group;" ::: "memory")
#define CP_WAIT0()  asm volatile("cp.async.wait_group 0;" ::: "memory")

__device__ __forceinline__ float tanh_fast(float x) {
    float ax = fabsf(x);
    float e  = __expf(2.0f * ax);
    float r  = 1.0f - 2.0f / (e + 1.0f);
    return copysignf(r, x);
}

// ===========================================================================
// Kernel 1: per-row mean/var, xhat = (x-mean)/(var+eps)^2  (ref quirk: squared)
// ===========================================================================
__global__ void __launch_bounds__(256) stats_kernel(const float* __restrict__ seq) {
    __shared__ float warp_s[8];
    __shared__ float stat[2];
    const int r   = blockIdx.x;
    const int tid = threadIdx.x;
    const float* x = seq + (size_t)r * Hn;
    float v0 = x[tid], v1 = x[tid + 256], v2 = x[tid + 512];
    float s = v0 + v1 + v2;
    #pragma unroll
    for (int o = 16; o; o >>= 1) s += __shfl_xor_sync(0xffffffffu, s, o);
    if ((tid & 31) == 0) warp_s[tid >> 5] = s;
    __syncthreads();
    if (tid == 0) {
        float t = 0.f;
        #pragma unroll
        for (int i = 0; i < 8; i++) t += warp_s[i];
        stat[0] = t * (1.0f / (float)Hn);
    }
    __syncthreads();
    const float mean = stat[0];
    float d0 = v0 - mean, d1 = v1 - mean, d2 = v2 - mean;
    float s2 = d0*d0 + d1*d1 + d2*d2;
    #pragma unroll
    for (int o = 16; o; o >>= 1) s2 += __shfl_xor_sync(0xffffffffu, s2, o);
    if ((tid & 31) == 0) warp_s[tid >> 5] = s2;
    __syncthreads();
    if (tid == 0) {
        float t = 0.f;
        #pragma unroll
        for (int i = 0; i < 8; i++) t += warp_s[i];
        float var = t * (1.0f / (float)Hn);
        float d = var + 1e-12f;
        stat[1] = 1.0f / (d * d);
    }
    __syncthreads();
    const float inv = stat[1];
    float* xo = g_xhat + (size_t)r * Hn;
    xo[tid]       = d0 * inv;
    xo[tid + 256] = d1 * inv;
    xo[tid + 512] = d2 * inv;
}

// ===========================================================================
// Kernel 2: NT GEMM -> g_gc / g_bc  (1024 x 768, K=768)
// ===========================================================================
__global__ void __launch_bounds__(256) cln_gemm_kernel(
    const float* __restrict__ seq,
    const float* __restrict__ w_gamma, const float* __restrict__ gamma,
    const float* __restrict__ w_beta,  const float* __restrict__ beta)
{
    __shared__ float Ash[16][132];
    __shared__ float Wsh[16][132];
    const int z = blockIdx.z;
    const float* W    = z ? w_beta : w_gamma;
    const float* bias = z ? beta   : gamma;
    float* dst        = z ? g_bc   : g_gc;
    const int r0 = blockIdx.x * 128;
    const int c0 = blockIdx.y * 128;
    const int tid = threadIdx.x;
    const int tx = tid & 15, ty = tid >> 4;
    const int lr = tid >> 1, kb = (tid & 1) * 8;

    float acc[8][8];
    #pragma unroll
    for (int u = 0; u < 8; u++)
        #pragma unroll
        for (int v = 0; v < 8; v++) acc[u][v] = 0.f;

    for (int k0 = 0; k0 < Hn; k0 += 16) {
        const float4* ap = (const float4*)(seq + (size_t)(r0 + lr) * Hn + k0 + kb);
        float4 a0 = ap[0], a1 = ap[1];
        const float4* wp = (const float4*)(W + (size_t)(c0 + lr) * Hn + k0 + kb);
        float4 w0 = wp[0], w1 = wp[1];
        Ash[kb+0][lr] = a0.x; Ash[kb+1][lr] = a0.y; Ash[kb+2][lr] = a0.z; Ash[kb+3][lr] = a0.w;
        Ash[kb+4][lr] = a1.x; Ash[kb+5][lr] = a1.y; Ash[kb+6][lr] = a1.z; Ash[kb+7][lr] = a1.w;
        Wsh[kb+0][lr] = w0.x; Wsh[kb+1][lr] = w0.y; Wsh[kb+2][lr] = w0.z; Wsh[kb+3][lr] = w0.w;
        Wsh[kb+4][lr] = w1.x; Wsh[kb+5][lr] = w1.y; Wsh[kb+6][lr] = w1.z; Wsh[kb+7][lr] = w1.w;
        __syncthreads();
        #pragma unroll
        for (int kk = 0; kk < 16; kk++) {
            float a[8], w[8];
            #pragma unroll
            for (int u = 0; u < 8; u++) a[u] = Ash[kk][ty + 16*u];
            #pragma unroll
            for (int v = 0; v < 8; v++) w[v] = Wsh[kk][tx + 16*v];
            #pragma unroll
            for (int u = 0; u < 8; u++)
                #pragma unroll
                for (int v = 0; v < 8; v++) acc[u][v] += a[u] * w[v];
        }
        __syncthreads();
    }
    #pragma unroll
    for (int u = 0; u < 8; u++) {
        int rr = r0 + ty + 16*u;
        #pragma unroll
        for (int v = 0; v < 8; v++) {
            int cc = c0 + tx + 16*v;
            dst[(size_t)rr * Hn + cc] = acc[u][v] + bias[cc];
        }
    }
}

// ===========================================================================
// Kernel 3: NN GEMM -> g_Cmat[k][r][m] = bc[r,:] @ Wk + bias_k
//   32-row x 128-col tiles, grid (32, 3) = 96 CTAs (was 24 -> latency bound).
// ===========================================================================
__global__ void __launch_bounds__(256) cmat_gemm_kernel(
    const float* __restrict__ w_ent,  const float* __restrict__ b_ent,
    const float* __restrict__ w_head, const float* __restrict__ b_head,
    const float* __restrict__ w_tail, const float* __restrict__ b_tail)
{
    __shared__ float Ash[16][36];
    __shared__ float Bsh[16][132];
    const int k = blockIdx.y;
    const float* W    = (k == 0) ? w_ent : (k == 1) ? w_head : w_tail;
    const float* bias = (k == 0) ? b_ent : (k == 1) ? b_head : b_tail;
    const int r0 = blockIdx.x * 32;
    const int tid = threadIdx.x;
    const int tx = tid & 15, ty = tid >> 4;
    const int arow = tid >> 2, akq = (tid & 3) * 4;
    const int lkk = tid >> 4, lm0 = (tid & 15) * 8;

    float acc[2][8];
    #pragma unroll
    for (int u = 0; u < 2; u++)
        #pragma unroll
        for (int v = 0; v < 8; v++) acc[u][v] = 0.f;

    for (int k0 = 0; k0 < Hn; k0 += 16) {
        if (tid < 128) {
            float4 a = *(const float4*)(g_bc + (size_t)(r0 + arow) * Hn + k0 + akq);
            Ash[akq+0][arow] = a.x; Ash[akq+1][arow] = a.y;
            Ash[akq+2][arow] = a.z; Ash[akq+3][arow] = a.w;
        }
        const float4* bp = (const float4*)(W + (size_t)(k0 + lkk) * Mn + lm0);
        float4 b0 = bp[0], b1 = bp[1];
        *(float4*)&Bsh[lkk][lm0]     = b0;
        *(float4*)&Bsh[lkk][lm0 + 4] = b1;
        __syncthreads();
        #pragma unroll
        for (int kk = 0; kk < 16; kk++) {
            float a0 = Ash[kk][ty], a1 = Ash[kk][ty + 16];
            #pragma unroll
            for (int v = 0; v < 8; v++) {
                float w = Bsh[kk][tx + 16*v];
                acc[0][v] += a0 * w;
                acc[1][v] += a1 * w;
            }
        }
        __syncthreads();
    }
    #pragma unroll
    for (int u = 0; u < 2; u++) {
        int rr = r0 + ty + 16*u;
        #pragma unroll
        for (int v = 0; v < 8; v++) {
            int cc = tx + 16*v;
            g_Cmat[((size_t)k * (Bn*Sn) + rr) * Mn + cc] = acc[u][v] + bias[cc];
        }
    }
}

// ===========================================================================
// Kernel 3b: transpose+split projection weights -> g_Wt_hi/lo [k][m][h] bf16
// ===========================================================================
__global__ void __launch_bounds__(256) wsplit_kernel(
    const float* __restrict__ w_ent,
    const float* __restrict__ w_head,
    const float* __restrict__ w_tail)
{
    int idx = blockIdx.x * 256 + threadIdx.x;
    if (idx >= 3 * Mn * Hn) return;
    int k  = idx / (Mn * Hn);
    int rm = idx - k * (Mn * Hn);
    int m  = rm / Hn;
    int h  = rm - m * Hn;
    const float* W = (k == 0) ? w_ent : (k == 1) ? w_head : w_tail;
    float v = W[(size_t)h * Mn + m];
    __nv_bfloat16 hi = __float2bfloat16(v);
    float lo = v - __bfloat162float(hi);
    g_Wt_hi[idx] = hi;
    g_Wt_lo[idx] = __float2bfloat16(lo);
}

// ===========================================================================
// Kernel 4: HMMA bf16x3 pair GEMM + fused tanh epilogue, triangular-trimmed.
//   4 variants on J0 = (i/32)*32: rows R = 128-J0, warp grid MWARP x NWARP,
//   warp tile = MT m-subtiles(16) x NTT n-subtiles(8), global n in [0,384).
//   Work factor vs full tile: mean 0.625.
// ===========================================================================
#define KC 32
#define NCH 24                    // 768/32
#define RSTRIDE 80                // 64B data + 16B pad (bank-disjoint frags)
#define W_TB   (384 * RSTRIDE)    // 30720 per (stage,hl)

template<int J0, int MWARP, int NWARP, int MT, int NTT>
__global__ void __launch_bounds__(256, 1) pair_mma_kernel(float* __restrict__ out) {
    constexpr int R      = 128 - J0;          // = MWARP*MT*16
    constexpr int A_TB   = R * RSTRIDE;
    constexpr int OFF_W  = 4 * A_TB;
    constexpr int OFF_GC = OFF_W + 4 * W_TB;
    constexpr int OFF_CM = OFF_GC + Hn * 4;

    extern __shared__ __align__(128) char dsm[];
    const uint32_t sB = smem_u32(dsm);
    float* gcs   = (float*)(dsm + OFF_GC);
    float* cmatS = (float*)(dsm + OFF_CM);

    const int tid  = threadIdx.x;
    const int wid  = tid >> 5;
    const int lane = tid & 31;
    const int g    = lane >> 2;
    const int tg   = lane & 3;
    const int wn   = wid % NWARP;
    const int wm   = wid / NWARP;
    const int i = J0 + (blockIdx.x & 31);
    const int b = blockIdx.x >> 5;

    {
        const float* gsrc = g_gc + (size_t)(b * Sn + i) * Hn;
        for (int t = tid; t < Hn; t += 256) gcs[t] = gsrc[t];
        for (int t = tid; t < 384; t += 256)
            cmatS[t] = g_Cmat[((size_t)(t >> 7) * (Bn*Sn) + b * Sn + i) * Mn + (t & 127)];
    }
    __syncthreads();

    float acc[MT][NTT][4];
    #pragma unroll
    for (int mt = 0; mt < MT; mt++)
        #pragma unroll
        for (int nt = 0; nt < NTT; nt++)
            #pragma unroll
            for (int r = 0; r < 4; r++) acc[mt][nt][r] = 0.f;

    const int fhalf = tid & 1;
    const int lrow  = tid >> 1;                       // A: row lrow of R; W: row lrow of 128
    const float* xrow = g_xhat + (size_t)(b * Sn + J0 + lrow) * Hn;

    auto fill = [&](int c, int s) {
        const int kc = c * KC;
        if (tid < 2 * R) {
            const float4* xp = (const float4*)(xrow + kc + fhalf * 16);
            const float4* gp = (const float4*)(gcs + kc + fhalf * 16);
            uint32_t hiP[8], loP[8];
            #pragma unroll
            for (int q = 0; q < 4; q++) {
                float4 xv = xp[q], gv = gp[q];
                float p0 = xv.x * gv.x, p1 = xv.y * gv.y;
                float p2 = xv.z * gv.z, p3 = xv.w * gv.w;
                uint32_t h01 = __byte_perm(__float_as_uint(p0), __float_as_uint(p1), 0x7632);
                uint32_t h23 = __byte_perm(__float_as_uint(p2), __float_as_uint(p3), 0x7632);
                float r0 = p0 - __uint_as_float(__float_as_uint(p0) & 0xffff0000u);
                float r1 = p1 - __uint_as_float(__float_as_uint(p1) & 0xffff0000u);
                float r2 = p2 - __uint_as_float(__float_as_uint(p2) & 0xffff0000u);
                float r3 = p3 - __uint_as_float(__float_as_uint(p3) & 0xffff0000u);
                __nv_bfloat162 l01 = __floats2bfloat162_rn(r0, r1);
                __nv_bfloat162 l23 = __floats2bfloat162_rn(r2, r3);
                hiP[2*q] = h01; hiP[2*q+1] = h23;
                loP[2*q] = *(uint32_t*)&l01; loP[2*q+1] = *(uint32_t*)&l23;
            }
            char* ab = dsm + s * (2 * A_TB);
            uint32_t ro = (uint32_t)(lrow * RSTRIDE + fhalf * 32);
            *(uint4*)(ab + ro)             = *(uint4*)&hiP[0];
            *(uint4*)(ab + ro + 16)        = *(uint4*)&hiP[4];
            *(uint4*)(ab + A_TB + ro)      = *(uint4*)&loP[0];
            *(uint4*)(ab + A_TB + ro + 16) = *(uint4*)&loP[4];
        }
        {
            uint32_t wb = sB + OFF_W + s * (2 * W_TB);
            uint32_t ro = (uint32_t)(lrow * RSTRIDE + fhalf * 32);
            #pragma unroll
            for (int h = 0; h < 3; h++) {
                size_t src = (size_t)(h * Mn + lrow) * Hn + kc + fhalf * 16;
                uint32_t d0 = wb + h * (128 * RSTRIDE) + ro;
                CP16(d0,          (const char*)(g_Wt_hi + src));
                CP16(d0 + 16,     (const char*)(g_Wt_hi + src + 8));
                CP16(d0 + W_TB,      (const char*)(g_Wt_lo + src));
                CP16(d0 + W_TB + 16, (const char*)(g_Wt_lo + src + 8));
            }
        }
        CP_COMMIT();
    };

    fill(0, 0);

    const uint32_t aRowBase = (uint32_t)((wm * MT * 16 + g) * RSTRIDE);
    const uint32_t wColBase = (uint32_t)((wn * NTT * 8 + g) * RSTRIDE);

    for (int c = 0; c < NCH; ++c) {
        const int s = c & 1;
        CP_WAIT0();
        __syncthreads();
        if (c + 1 < NCH) fill(c + 1, s ^ 1);

        const uint32_t aH = sB + s * (2 * A_TB);
        const uint32_t aL = aH + A_TB;
        const uint32_t wH = sB + OFF_W + s * (2 * W_TB);
        const uint32_t wL = wH + W_TB;

        #pragma unroll
        for (int ks = 0; ks < 2; ks++) {
            const uint32_t ko = ks * 32 + tg * 4;
            uint32_t Ah[MT][4], Al[MT][4];
            #pragma unroll
            for (int mt = 0; mt < MT; mt++) {
                uint32_t base = aRowBase + mt * (16 * RSTRIDE) + ko;
                Ah[mt][0] = lds32(aH + base);
                Ah[mt][1] = lds32(aH + base + 8 * RSTRIDE);
                Ah[mt][2] = lds32(aH + base + 16);
                Ah[mt][3] = lds32(aH + base + 8 * RSTRIDE + 16);
                Al[mt][0] = lds32(aL + base);
                Al[mt][1] = lds32(aL + base + 8 * RSTRIDE);
                Al[mt][2] = lds32(aL + base + 16);
                Al[mt][3] = lds32(aL + base + 8 * RSTRIDE + 16);
            }
            #pragma unroll
            for (int nt = 0; nt < NTT; nt++) {
                uint32_t wb = wColBase + nt * (8 * RSTRIDE) + ko;
                uint32_t Bh0 = lds32(wH + wb);
                uint32_t Bh1 = lds32(wH + wb + 16);
                uint32_t Bl0 = lds32(wL + wb);
                uint32_t Bl1 = lds32(wL + wb + 16);
                #pragma unroll
                for (int mt = 0; mt < MT; mt++) {
                    float* d = acc[mt][nt];
                    mma16816(d[0], d[1], d[2], d[3],
                             Ah[mt][0], Ah[mt][1], Ah[mt][2], Ah[mt][3], Bh0, Bh1);
                    mma16816(d[0], d[1], d[2], d[3],
                             Ah[mt][0], Ah[mt][1], Ah[mt][2], Ah[mt][3], Bl0, Bl1);
                    mma16816(d[0], d[1], d[2], d[3],
                             Al[mt][0], Al[mt][1], Al[mt][2], Al[mt][3], Bh0, Bh1);
                }
            }
        }
        __syncthreads();
    }

    // ---- epilogue: + Cmat bias, tanh, masked stores ----
    const int offi = i * Sn - (i * (i - 1)) / 2;
    #pragma unroll
    for (int mt = 0; mt < MT; mt++) {
        const int j0r = J0 + wm * MT * 16 + mt * 16 + g;
        #pragma unroll
        for (int nt = 0; nt < NTT; nt++) {
            const int n0 = wn * NTT * 8 + nt * 8 + tg * 2;
            const int head = n0 >> 7;
            const int m = n0 & 127;
            const float cm0 = cmatS[n0];
            const float cm1 = cmatS[n0 + 1];
            const float* d = acc[mt][nt];
            const size_t hb = (size_t)(head * Bn + b) * Pn;
            if (j0r >= i) {
                float2 v0 = make_float2(tanh_fast(d[0] + cm0), tanh_fast(d[1] + cm1));
                *(float2*)(out + (hb + (size_t)(offi - i + j0r)) * Mn + m) = v0;
            }
            const int j1r = j0r + 8;
            if (j1r >= i) {
                float2 v1 = make_float2(tanh_fast(d[2] + cm0), tanh_fast(d[3] + cm1));
                *(float2*)(out + (hb + (size_t)(offi - i + j1r)) * Mn + m) = v1;
            }
        }
    }
}

// host-side smem size per variant
static inline int pair_smem(int R) { return 320 * R + 4 * W_TB + Hn * 4 + 384 * 4; }

// ===========================================================================
extern "C" void kernel_launch(void* const* d_in, const int* in_sizes, int n_in,
                              void* d_out, int out_size) {
    (void)in_sizes; (void)n_in; (void)out_size;
    const float* seq     = (const float*)d_in[0];
    const float* gamma   = (const float*)d_in[1];
    const float* beta    = (const float*)d_in[2];
    const float* w_beta  = (const float*)d_in[3];
    const float* w_gamma = (const float*)d_in[4];
    const float* w_ent   = (const float*)d_in[5];
    const float* b_ent   = (const float*)d_in[6];
    const float* w_head  = (const float*)d_in[7];
    const float* b_head  = (const float*)d_in[8];
    const float* w_tail  = (const float*)d_in[9];
    const float* b_tail  = (const float*)d_in[10];
    float* out = (float*)d_out;

    cudaFuncSetAttribute(pair_mma_kernel<0,4,2,2,24>,
                         cudaFuncAttributeMaxDynamicSharedMemorySize, pair_smem(128));
    cudaFuncSetAttribute(pair_mma_kernel<32,2,4,3,12>,
                         cudaFuncAttributeMaxDynamicSharedMemorySize, pair_smem(96));
    cudaFuncSetAttribute(pair_mma_kernel<64,2,4,2,12>,
                         cudaFuncAttributeMaxDynamicSharedMemorySize, pair_smem(64));
    cudaFuncSetAttribute(pair_mma_kernel<96,1,8,2,6>,
                         cudaFuncAttributeMaxDynamicSharedMemorySize, pair_smem(32));

    stats_kernel<<<Bn * Sn, 256>>>(seq);
    cln_gemm_kernel<<<dim3(8, 6, 2), 256>>>(seq, w_gamma, gamma, w_beta, beta);
    wsplit_kernel<<<(3 * Mn * Hn + 255) / 256, 256>>>(w_ent, w_head, w_tail);
    cmat_gemm_kernel<<<dim3(32, 3), 256>>>(w_ent, b_ent, w_head, b_head, w_tail, b_tail);

    pair_mma_kernel<0,4,2,2,24><<<256, 256, pair_smem(128)>>>(out);
    pair_mma_kernel<32,2,4,3,12><<<256, 256, pair_smem(96)>>>(out);
    pair_mma_kernel<64,2,4,2,12><<<256, 256, pair_smem(64)>>>(out);
    pair_mma_kernel<96,1,8,2,6><<<256, 256, pair_smem(32)>>>(out);
}

// round 7
// speedup vs baseline: 2.4480x; 1.0781x over previous
#include <cuda_runtime.h>
#include <cuda_bf16.h>
#include <math.h>
#include <stdint.h>

// Problem constants: B=8, S=128, H=768, M=128, P = S(S+1)/2 = 8256
#define Bn 8
#define Sn 128
#define Hn 768
#define Mn 128
#define Pn 8256

// Scratch (__device__ globals; allocation-free rule)
__device__ float g_xhat[Bn*Sn*Hn];                         // (x-mean)/(var+eps)^2
__device__ float g_gc  [Bn*Sn*Hn];                         // seq @ w_gamma^T + gamma
__device__ float g_bc  [Bn*Sn*Hn];                         // seq @ w_beta^T  + beta
__device__ float g_Cmat[3*Bn*Sn*Mn];                       // bc @ W_k + bias_k
__device__ __align__(16) __nv_bfloat16 g_Wt_hi[3*Mn*Hn];   // W_k^T hi  [k][m][h]
__device__ __align__(16) __nv_bfloat16 g_Wt_lo[3*Mn*Hn];   // W_k^T lo
__device__ __align__(16) __nv_bfloat16 g_seq_hi[Bn*Sn*Hn]; // seq split hi
__device__ __align__(16) __nv_bfloat16 g_seq_lo[Bn*Sn*Hn];
__device__ __align__(16) __nv_bfloat16 g_Wg_hi[Hn*Hn];     // w_gamma [o][h] hi
__device__ __align__(16) __nv_bfloat16 g_Wg_lo[Hn*Hn];
__device__ __align__(16) __nv_bfloat16 g_Wb_hi[Hn*Hn];     // w_beta  [o][h] hi
__device__ __align__(16) __nv_bfloat16 g_Wb_lo[Hn*Hn];

// ---------------------------------------------------------------------------
__device__ __forceinline__ uint32_t smem_u32(const void* p) {
    uint32_t a;
    asm("{ .reg .u64 t; cvta.to.shared.u64 t, %1; cvt.u32.u64 %0, t; }" : "=r"(a) : "l"(p));
    return a;
}
__device__ __forceinline__ void ldmx4(uint32_t& r0, uint32_t& r1, uint32_t& r2, uint32_t& r3,
                                      uint32_t a) {
    asm volatile("ldmatrix.sync.aligned.m8n8.x4.shared.b16 {%0,%1,%2,%3}, [%4];"
                 : "=r"(r0), "=r"(r1), "=r"(r2), "=r"(r3) : "r"(a));
}
__device__ __forceinline__ void mma16816(float* d,
                                         const uint32_t* a, uint32_t b0, uint32_t b1) {
    asm volatile(
        "mma.sync.aligned.m16n8k16.row.col.f32.bf16.bf16.f32 "
        "{%0,%1,%2,%3},{%4,%5,%6,%7},{%8,%9},{%0,%1,%2,%3};"
        : "+f"(d[0]), "+f"(d[1]), "+f"(d[2]), "+f"(d[3])
        : "r"(a[0]), "r"(a[1]), "r"(a[2]), "r"(a[3]), "r"(b0), "r"(b1));
}
#define CP16(dst, src) \
    asm volatile("cp.async.cg.shared.global [%0], [%1], 16;" :: "r"(dst), "l"(src) : "memory")
#define CP_COMMIT() asm volatile("cp.async.commit_group;" ::: "memory")
#define CP_WAITG(n) asm volatile("cp.async.wait_group %0;" :: "n"(n) : "memory")

__device__ __forceinline__ float tanh_fast(float x) {
    float ax = fabsf(x);
    float e  = __expf(2.0f * ax);
    float r  = 1.0f - 2.0f / (e + 1.0f);
    return copysignf(r, x);
}

#define RS 80                      // smem row stride: 64B data + 16B pad
#define KC 32
#define NCH 24                     // 768/32
#define WTB (128 * RS)             // 10240: one 128-row k-chunk tile

// ===========================================================================
// Kernel 1: stats + xhat + seq hi/lo splits
// ===========================================================================
__global__ void __launch_bounds__(256) stats_kernel(const float* __restrict__ seq) {
    __shared__ float warp_s[8];
    __shared__ float stat[2];
    const int r   = blockIdx.x;
    const int tid = threadIdx.x;
    const float* x = seq + (size_t)r * Hn;
    float v0 = x[tid], v1 = x[tid + 256], v2 = x[tid + 512];

    // seq splits (raw values, rounded hi)
    {
        __nv_bfloat16 h0 = __float2bfloat16(v0);
        __nv_bfloat16 h1 = __float2bfloat16(v1);
        __nv_bfloat16 h2 = __float2bfloat16(v2);
        g_seq_hi[(size_t)r*Hn + tid]       = h0;
        g_seq_hi[(size_t)r*Hn + tid + 256] = h1;
        g_seq_hi[(size_t)r*Hn + tid + 512] = h2;
        g_seq_lo[(size_t)r*Hn + tid]       = __float2bfloat16(v0 - __bfloat162float(h0));
        g_seq_lo[(size_t)r*Hn + tid + 256] = __float2bfloat16(v1 - __bfloat162float(h1));
        g_seq_lo[(size_t)r*Hn + tid + 512] = __float2bfloat16(v2 - __bfloat162float(h2));
    }

    float s = v0 + v1 + v2;
    #pragma unroll
    for (int o = 16; o; o >>= 1) s += __shfl_xor_sync(0xffffffffu, s, o);
    if ((tid & 31) == 0) warp_s[tid >> 5] = s;
    __syncthreads();
    if (tid == 0) {
        float t = 0.f;
        #pragma unroll
        for (int i = 0; i < 8; i++) t += warp_s[i];
        stat[0] = t * (1.0f / (float)Hn);
    }
    __syncthreads();
    const float mean = stat[0];
    float d0 = v0 - mean, d1 = v1 - mean, d2 = v2 - mean;
    float s2 = d0*d0 + d1*d1 + d2*d2;
    #pragma unroll
    for (int o = 16; o; o >>= 1) s2 += __shfl_xor_sync(0xffffffffu, s2, o);
    if ((tid & 31) == 0) warp_s[tid >> 5] = s2;
    __syncthreads();
    if (tid == 0) {
        float t = 0.f;
        #pragma unroll
        for (int i = 0; i < 8; i++) t += warp_s[i];
        float var = t * (1.0f / (float)Hn);
        float d = var + 1e-12f;
        stat[1] = 1.0f / (d * d);                 // ref quirk: (var+eps)^2, no sqrt
    }
    __syncthreads();
    const float inv = stat[1];
    float* xo = g_xhat + (size_t)r * Hn;
    xo[tid]       = d0 * inv;
    xo[tid + 256] = d1 * inv;
    xo[tid + 512] = d2 * inv;
}

// ===========================================================================
// Kernel 1b/1c: weight splits
// ===========================================================================
__global__ void __launch_bounds__(256) wsplit_proj_kernel(
    const float* __restrict__ w_ent,
    const float* __restrict__ w_head,
    const float* __restrict__ w_tail)
{
    int idx = blockIdx.x * 256 + threadIdx.x;
    if (idx >= 3 * Mn * Hn) return;
    int k  = idx / (Mn * Hn);
    int rm = idx - k * (Mn * Hn);
    int m  = rm / Hn;
    int h  = rm - m * Hn;
    const float* W = (k == 0) ? w_ent : (k == 1) ? w_head : w_tail;
    float v = W[(size_t)h * Mn + m];              // transpose: [h][m] -> [m][h]
    __nv_bfloat16 hi = __float2bfloat16(v);
    g_Wt_hi[idx] = hi;
    g_Wt_lo[idx] = __float2bfloat16(v - __bfloat162float(hi));
}

__global__ void __launch_bounds__(256) wsplit_cln_kernel(
    const float* __restrict__ w_gamma, const float* __restrict__ w_beta)
{
    int idx = blockIdx.x * 256 + threadIdx.x;
    if (idx >= 2 * Hn * Hn) return;
    int z = idx / (Hn * Hn);
    int e = idx - z * (Hn * Hn);
    float v = (z ? w_beta : w_gamma)[e];
    __nv_bfloat16 hi = __float2bfloat16(v);
    __nv_bfloat16 lo = __float2bfloat16(v - __bfloat162float(hi));
    if (z) { g_Wb_hi[e] = hi; g_Wb_lo[e] = lo; }
    else   { g_Wg_hi[e] = hi; g_Wg_lo[e] = lo; }
}

// ===========================================================================
// Kernel 2: cln NT GEMM via bf16x3 HMMA -> g_gc / g_bc
//   C[r,o] = seq[r,:] . W[o,:] + bias[o];  128x128 tiles, grid (8,6,2).
// ===========================================================================
#define CLN_ATB 10240
#define CLN_WOFF (4 * CLN_ATB)
#define CLN_BIAS (CLN_WOFF + 4 * WTB)
#define CLN_SMEM (CLN_BIAS + 512 + 16)

__global__ void __launch_bounds__(256, 2) cln_hmma_kernel(
    const float* __restrict__ gamma, const float* __restrict__ beta)
{
    extern __shared__ __align__(128) char dsm[];
    const uint32_t sB = smem_u32(dsm);
    float* biasS = (float*)(dsm + CLN_BIAS);

    const int z  = blockIdx.z;
    const __nv_bfloat16* Wh_g = z ? g_Wb_hi : g_Wg_hi;
    const __nv_bfloat16* Wl_g = z ? g_Wb_lo : g_Wg_lo;
    const float* bias = z ? beta : gamma;
    float* dst        = z ? g_bc : g_gc;

    const int r0 = blockIdx.x * 128;
    const int c0 = blockIdx.y * 128;
    const int tid  = threadIdx.x;
    const int wid  = tid >> 5;
    const int lane = tid & 31;
    const int g    = lane >> 2;
    const int tg   = lane & 3;
    const int wm   = wid >> 1, wn = wid & 1;

    if (tid < 128) biasS[tid] = bias[c0 + tid];

    float acc[2][8][4];
    #pragma unroll
    for (int mt = 0; mt < 2; mt++)
        #pragma unroll
        for (int nt = 0; nt < 8; nt++)
            #pragma unroll
            for (int r = 0; r < 4; r++) acc[mt][nt][r] = 0.f;

    const int lrow = tid >> 1, fhalf = tid & 1;
    const uint32_t dro = (uint32_t)(lrow * RS + fhalf * 32);

    auto fill = [&](int c, int s) {
        const int kc = c * KC;
        size_t asrc = (size_t)(r0 + lrow) * Hn + kc + fhalf * 16;
        size_t wsrc = (size_t)(c0 + lrow) * Hn + kc + fhalf * 16;
        uint32_t ad = sB + s * (2 * CLN_ATB) + dro;
        uint32_t wd = sB + CLN_WOFF + s * (2 * WTB) + dro;
        CP16(ad,                  (const char*)(g_seq_hi + asrc));
        CP16(ad + 16,             (const char*)(g_seq_hi + asrc + 8));
        CP16(ad + CLN_ATB,        (const char*)(g_seq_lo + asrc));
        CP16(ad + CLN_ATB + 16,   (const char*)(g_seq_lo + asrc + 8));
        CP16(wd,                  (const char*)(Wh_g + wsrc));
        CP16(wd + 16,             (const char*)(Wh_g + wsrc + 8));
        CP16(wd + WTB,            (const char*)(Wl_g + wsrc));
        CP16(wd + WTB + 16,       (const char*)(Wl_g + wsrc + 8));
        CP_COMMIT();
    };

    const uint32_t loff = (uint32_t)(((lane & 7) + ((lane >> 3) & 1) * 8) * RS + (lane >> 4) * 16);

    fill(0, 0);
    for (int c = 0; c < NCH; ++c) {
        const int s = c & 1;
        if (c + 1 < NCH) { __syncthreads(); fill(c + 1, s ^ 1); CP_WAITG(1); }
        else             { CP_WAITG(0); }
        __syncthreads();

        const uint32_t aH = sB + s * (2 * CLN_ATB);
        const uint32_t aL = aH + CLN_ATB;
        const uint32_t wH = sB + CLN_WOFF + s * (2 * WTB);
        const uint32_t wL = wH + WTB;

        #pragma unroll
        for (int ks = 0; ks < 2; ks++) {
            const uint32_t ko = ks * 32 + loff;
            uint32_t Ah[2][4], Al[2][4];
            #pragma unroll
            for (int mt = 0; mt < 2; mt++) {
                uint32_t ab = (uint32_t)((wm * 32 + mt * 16) * RS) + ko;
                ldmx4(Ah[mt][0], Ah[mt][1], Ah[mt][2], Ah[mt][3], aH + ab);
                ldmx4(Al[mt][0], Al[mt][1], Al[mt][2], Al[mt][3], aL + ab);
            }
            #pragma unroll
            for (int ntp = 0; ntp < 4; ntp++) {
                uint32_t wb = (uint32_t)((wn * 64 + ntp * 16) * RS) + ko;
                uint32_t h0, h1, h2, h3, l0, l1, l2, l3;
                ldmx4(h0, h1, h2, h3, wH + wb);
                ldmx4(l0, l1, l2, l3, wL + wb);
                #pragma unroll
                for (int mt = 0; mt < 2; mt++) {
                    mma16816(acc[mt][2*ntp],   Ah[mt], h0, h2);
                    mma16816(acc[mt][2*ntp],   Ah[mt], l0, l2);
                    mma16816(acc[mt][2*ntp],   Al[mt], h0, h2);
                    mma16816(acc[mt][2*ntp+1], Ah[mt], h1, h3);
                    mma16816(acc[mt][2*ntp+1], Ah[mt], l1, l3);
                    mma16816(acc[mt][2*ntp+1], Al[mt], h1, h3);
                }
            }
        }
    }

    #pragma unroll
    for (int mt = 0; mt < 2; mt++) {
        const int row = r0 + wm * 32 + mt * 16 + g;
        #pragma unroll
        for (int nt = 0; nt < 8; nt++) {
            const int cc = wn * 64 + nt * 8 + tg * 2;
            const float b0v = biasS[cc], b1v = biasS[cc + 1];
            const float* d = acc[mt][nt];
            *(float2*)(dst + (size_t)row * Hn + c0 + cc) =
                make_float2(d[0] + b0v, d[1] + b1v);
            *(float2*)(dst + (size_t)(row + 8) * Hn + c0 + cc) =
                make_float2(d[2] + b0v, d[3] + b1v);
        }
    }
}

// ===========================================================================
// Kernel 3: cmat NN GEMM (fp32) -> g_Cmat, 16-row tiles, grid (64,3)
// ===========================================================================
__global__ void __launch_bounds__(256) cmat_gemm_kernel(
    const float* __restrict__ w_ent,  const float* __restrict__ b_ent,
    const float* __restrict__ w_head, const float* __restrict__ b_head,
    const float* __restrict__ w_tail, const float* __restrict__ b_tail)
{
    __shared__ float Ash[32][17];
    __shared__ float Bsh[32][132];
    const int k = blockIdx.y;
    const float* W    = (k == 0) ? w_ent : (k == 1) ? w_head : w_tail;
    const float* bias = (k == 0) ? b_ent : (k == 1) ? b_head : b_tail;
    const int r0 = blockIdx.x * 16;
    const int tid = threadIdx.x;
    const int tx = tid & 15, ty = tid >> 4;
    const int arow = tid & 15, akq = tid >> 4;       // A: 2 floats at k=2*akq
    const int bk = tid >> 4, bm0 = (tid & 15) * 8;   // B: rows bk, bk+16

    float acc[8];
    #pragma unroll
    for (int v = 0; v < 8; v++) acc[v] = 0.f;

    for (int k0 = 0; k0 < Hn; k0 += 32) {
        float2 a = *(const float2*)(g_bc + (size_t)(r0 + arow) * Hn + k0 + 2 * akq);
        Ash[2*akq][arow]   = a.x;
        Ash[2*akq+1][arow] = a.y;
        const float4* bp0 = (const float4*)(W + (size_t)(k0 + bk) * Mn + bm0);
        const float4* bp1 = (const float4*)(W + (size_t)(k0 + bk + 16) * Mn + bm0);
        *(float4*)&Bsh[bk][bm0]        = bp0[0];
        *(float4*)&Bsh[bk][bm0 + 4]    = bp0[1];
        *(float4*)&Bsh[bk+16][bm0]     = bp1[0];
        *(float4*)&Bsh[bk+16][bm0 + 4] = bp1[1];
        __syncthreads();
        #pragma unroll
        for (int kk = 0; kk < 32; kk++) {
            float a0 = Ash[kk][ty];
            #pragma unroll
            for (int v = 0; v < 8; v++) acc[v] += a0 * Bsh[kk][tx + 16*v];
        }
        __syncthreads();
    }
    {
        int rr = r0 + ty;
        #pragma unroll
        for (int v = 0; v < 8; v++) {
            int cc = tx + 16*v;
            g_Cmat[((size_t)k * (Bn*Sn) + rr) * Mn + cc] = acc[v] + bias[cc];
        }
    }
}

// ===========================================================================
// Kernel 4: pair GEMM, head-split, bf16x3 HMMA + ldmatrix, triangular-trimmed.
//   One CTA per (b, i, head). Rows j in [J0,128), cols m in [0,128).
//   acc <= 64 regs (no spills). 2 CTAs/SM.
// ===========================================================================
template<int J0, int MWARP, int NWARP, int MT, int NTP>
__global__ void __launch_bounds__(256, 2) pair_mma_kernel(float* __restrict__ out) {
    constexpr int R    = 128 - J0;
    constexpr int ATB  = R * RS;
    constexpr int WOFF = 4 * ATB;
    constexpr int GOFF = WOFF + 4 * WTB;
    constexpr int COFF = GOFF + Hn * 4;

    extern __shared__ __align__(128) char dsm[];
    const uint32_t sB = smem_u32(dsm);
    float* gcs = (float*)(dsm + GOFF);
    float* cmS = (float*)(dsm + COFF);

    const int tid  = threadIdx.x;
    const int wid  = tid >> 5;
    const int lane = tid & 31;
    const int g    = lane >> 2;
    const int tg   = lane & 3;
    const int wn   = wid % NWARP;
    const int wm   = wid / NWARP;
    const int i    = J0 + (blockIdx.x & 31);
    const int b    = blockIdx.x >> 5;
    const int head = blockIdx.y;

    {
        const float* gsrc = g_gc + (size_t)(b * Sn + i) * Hn;
        for (int t = tid; t < Hn; t += 256) gcs[t] = gsrc[t];
        if (tid < 128)
            cmS[tid] = g_Cmat[((size_t)head * (Bn*Sn) + b * Sn + i) * Mn + tid];
    }
    __syncthreads();

    float acc[MT][2*NTP][4];
    #pragma unroll
    for (int mt = 0; mt < MT; mt++)
        #pragma unroll
        for (int nt = 0; nt < 2*NTP; nt++)
            #pragma unroll
            for (int r = 0; r < 4; r++) acc[mt][nt][r] = 0.f;

    const int lrow = tid >> 1, fhalf = tid & 1;
    const uint32_t dro = (uint32_t)(lrow * RS + fhalf * 32);
    const float* xrow = g_xhat + (size_t)(b * Sn + J0 + lrow) * Hn;

    auto fill = [&](int c, int s) {
        const int kc = c * KC;
        if (tid < 2 * R) {
            const float4* xp = (const float4*)(xrow + kc + fhalf * 16);
            const float4* gp = (const float4*)(gcs + kc + fhalf * 16);
            char* ahi = dsm + s * (2 * ATB);
            #pragma unroll
            for (int q = 0; q < 4; q++) {
                float4 xv = xp[q], gv = gp[q];
                float p0 = xv.x * gv.x, p1 = xv.y * gv.y;
                float p2 = xv.z * gv.z, p3 = xv.w * gv.w;
                uint2 H, L;
                H.x = __byte_perm(__float_as_uint(p0), __float_as_uint(p1), 0x7632);
                H.y = __byte_perm(__float_as_uint(p2), __float_as_uint(p3), 0x7632);
                float r0 = p0 - __uint_as_float(__float_as_uint(p0) & 0xffff0000u);
                float r1 = p1 - __uint_as_float(__float_as_uint(p1) & 0xffff0000u);
                float r2 = p2 - __uint_as_float(__float_as_uint(p2) & 0xffff0000u);
                float r3 = p3 - __uint_as_float(__float_as_uint(p3) & 0xffff0000u);
                __nv_bfloat162 l01 = __floats2bfloat162_rn(r0, r1);
                __nv_bfloat162 l23 = __floats2bfloat162_rn(r2, r3);
                L.x = *(uint32_t*)&l01; L.y = *(uint32_t*)&l23;
                *(uint2*)(ahi + dro + q * 8)       = H;
                *(uint2*)(ahi + ATB + dro + q * 8) = L;
            }
        }
        {
            size_t wsrc = (size_t)(head * Mn + lrow) * Hn + kc + fhalf * 16;
            uint32_t wd = sB + WOFF + s * (2 * WTB) + dro;
            CP16(wd,            (const char*)(g_Wt_hi + wsrc));
            CP16(wd + 16,       (const char*)(g_Wt_hi + wsrc + 8));
            CP16(wd + WTB,      (const char*)(g_Wt_lo + wsrc));
            CP16(wd + WTB + 16, (const char*)(g_Wt_lo + wsrc + 8));
        }
        CP_COMMIT();
    };

    const uint32_t loff = (uint32_t)(((lane & 7) + ((lane >> 3) & 1) * 8) * RS + (lane >> 4) * 16);

    fill(0, 0);
    for (int c = 0; c < NCH; ++c) {
        const int s = c & 1;
        if (c + 1 < NCH) { __syncthreads(); fill(c + 1, s ^ 1); CP_WAITG(1); }
        else             { CP_WAITG(0); }
        __syncthreads();

        const uint32_t aH = sB + s * (2 * ATB);
        const uint32_t aL = aH + ATB;
        const uint32_t wH = sB + WOFF + s * (2 * WTB);
        const uint32_t wL = wH + WTB;

        #pragma unroll
        for (int ks = 0; ks < 2; ks++) {
            const uint32_t ko = ks * 32 + loff;
            uint32_t Ah[MT][4], Al[MT][4];
            #pragma unroll
            for (int mt = 0; mt < MT; mt++) {
                uint32_t ab = (uint32_t)((wm * MT * 16 + mt * 16) * RS) + ko;
                ldmx4(Ah[mt][0], Ah[mt][1], Ah[mt][2], Ah[mt][3], aH + ab);
                ldmx4(Al[mt][0], Al[mt][1], Al[mt][2], Al[mt][3], aL + ab);
            }
            #pragma unroll
            for (int ntp = 0; ntp < NTP; ntp++) {
                uint32_t wb = (uint32_t)((wn * NTP * 16 + ntp * 16) * RS) + ko;
                uint32_t h0, h1, h2, h3, l0, l1, l2, l3;
                ldmx4(h0, h1, h2, h3, wH + wb);
                ldmx4(l0, l1, l2, l3, wL + wb);
                #pragma unroll
                for (int mt = 0; mt < MT; mt++) {
                    mma16816(acc[mt][2*ntp],   Ah[mt], h0, h2);
                    mma16816(acc[mt][2*ntp],   Ah[mt], l0, l2);
                    mma16816(acc[mt][2*ntp],   Al[mt], h0, h2);
                    mma16816(acc[mt][2*ntp+1], Ah[mt], h1, h3);
                    mma16816(acc[mt][2*ntp+1], Ah[mt], l1, l3);
                    mma16816(acc[mt][2*ntp+1], Al[mt], h1, h3);
                }
            }
        }
    }

    // epilogue
    const int offi = i * Sn - (i * (i - 1)) / 2;
    const size_t hb = (size_t)(head * Bn + b) * Pn;
    #pragma unroll
    for (int mt = 0; mt < MT; mt++) {
        const int j0r = J0 + wm * MT * 16 + mt * 16 + g;
        #pragma unroll
        for (int nt = 0; nt < 2*NTP; nt++) {
            const int m = wn * NTP * 16 + nt * 8 + tg * 2;
            const float cm0 = cmS[m], cm1 = cmS[m + 1];
            const float* d = acc[mt][nt];
            if (j0r >= i) {
                *(float2*)(out + (hb + (size_t)(offi - i + j0r)) * Mn + m) =
                    make_float2(tanh_fast(d[0] + cm0), tanh_fast(d[1] + cm1));
            }
            const int j1r = j0r + 8;
            if (j1r >= i) {
                *(float2*)(out + (hb + (size_t)(offi - i + j1r)) * Mn + m) =
                    make_float2(tanh_fast(d[2] + cm0), tanh_fast(d[3] + cm1));
            }
        }
    }
}

static inline int pair_smem(int R) { return 4 * R * RS + 4 * WTB + Hn * 4 + 512 + 16; }

// ===========================================================================
extern "C" void kernel_launch(void* const* d_in, const int* in_sizes, int n_in,
                              void* d_out, int out_size) {
    (void)in_sizes; (void)n_in; (void)out_size;
    const float* seq     = (const float*)d_in[0];
    const float* gamma   = (const float*)d_in[1];
    const float* beta    = (const float*)d_in[2];
    const float* w_beta  = (const float*)d_in[3];
    const float* w_gamma = (const float*)d_in[4];
    const float* w_ent   = (const float*)d_in[5];
    const float* b_ent   = (const float*)d_in[6];
    const float* w_head  = (const float*)d_in[7];
    const float* b_head  = (const float*)d_in[8];
    const float* w_tail  = (const float*)d_in[9];
    const float* b_tail  = (const float*)d_in[10];
    float* out = (float*)d_out;

    cudaFuncSetAttribute(cln_hmma_kernel,
                         cudaFuncAttributeMaxDynamicSharedMemorySize, CLN_SMEM);
    cudaFuncSetAttribute(pair_mma_kernel<0,4,2,2,4>,
                         cudaFuncAttributeMaxDynamicSharedMemorySize, pair_smem(128));
    cudaFuncSetAttribute(pair_mma_kernel<32,2,4,3,2>,
                         cudaFuncAttributeMaxDynamicSharedMemorySize, pair_smem(96));
    cudaFuncSetAttribute(pair_mma_kernel<64,2,4,2,2>,
                         cudaFuncAttributeMaxDynamicSharedMemorySize, pair_smem(64));
    cudaFuncSetAttribute(pair_mma_kernel<96,1,8,2,1>,
                         cudaFuncAttributeMaxDynamicSharedMemorySize, pair_smem(32));

    stats_kernel<<<Bn * Sn, 256>>>(seq);
    wsplit_cln_kernel<<<(2 * Hn * Hn + 255) / 256, 256>>>(w_gamma, w_beta);
    wsplit_proj_kernel<<<(3 * Mn * Hn + 255) / 256, 256>>>(w_ent, w_head, w_tail);
    cln_hmma_kernel<<<dim3(8, 6, 2), 256, CLN_SMEM>>>(gamma, beta);
    cmat_gemm_kernel<<<dim3(64, 3), 256>>>(w_ent, b_ent, w_head, b_head, w_tail, b_tail);

    pair_mma_kernel<0,4,2,2,4><<<dim3(256, 3), 256, pair_smem(128)>>>(out);
    pair_mma_kernel<32,2,4,3,2><<<dim3(256, 3), 256, pair_smem(96)>>>(out);
    pair_mma_kernel<64,2,4,2,2><<<dim3(256, 3), 256, pair_smem(64)>>>(out);
    pair_mma_kernel<96,1,8,2,1><<<dim3(256, 3), 256, pair_smem(32)>>>(out);
}

// round 8
// speedup vs baseline: 3.9370x; 1.6082x over previous
#include <cuda_runtime.h>
#include <cuda_bf16.h>
#include <cuda_fp16.h>
#include <math.h>
#include <stdint.h>

// Problem constants: B=8, S=128, H=768, M=128, P = S(S+1)/2 = 8256
#define Bn 8
#define Sn 128
#define Hn 768
#define Mn 128
#define Pn 8256

// Scratch (__device__ globals; allocation-free rule)
__device__ float g_xhat[Bn*Sn*Hn];                         // (x-mean)/(var+eps)^2
__device__ float g_gc  [Bn*Sn*Hn];                         // seq @ w_gamma^T + gamma
__device__ float g_bc  [Bn*Sn*Hn];                         // seq @ w_beta^T  + beta
__device__ float g_Cmat[3*Bn*Sn*Mn];                       // bc @ W_k + bias_k
__device__ __align__(16) __half g_Wth[3*Mn*Hn];            // W_k^T fp16 [k][m][h]
__device__ __align__(16) __nv_bfloat16 g_seq_hi[Bn*Sn*Hn]; // seq split hi (cln)
__device__ __align__(16) __nv_bfloat16 g_seq_lo[Bn*Sn*Hn];
__device__ __align__(16) __nv_bfloat16 g_Wg_hi[Hn*Hn];     // w_gamma [o][h] hi
__device__ __align__(16) __nv_bfloat16 g_Wg_lo[Hn*Hn];
__device__ __align__(16) __nv_bfloat16 g_Wb_hi[Hn*Hn];     // w_beta  [o][h] hi
__device__ __align__(16) __nv_bfloat16 g_Wb_lo[Hn*Hn];

// ---------------------------------------------------------------------------
__device__ __forceinline__ uint32_t smem_u32(const void* p) {
    uint32_t a;
    asm("{ .reg .u64 t; cvta.to.shared.u64 t, %1; cvt.u32.u64 %0, t; }" : "=r"(a) : "l"(p));
    return a;
}
__device__ __forceinline__ void ldmx4(uint32_t& r0, uint32_t& r1, uint32_t& r2, uint32_t& r3,
                                      uint32_t a) {
    asm volatile("ldmatrix.sync.aligned.m8n8.x4.shared.b16 {%0,%1,%2,%3}, [%4];"
                 : "=r"(r0), "=r"(r1), "=r"(r2), "=r"(r3) : "r"(a));
}
__device__ __forceinline__ void mma_bf(float* d, const uint32_t* a, uint32_t b0, uint32_t b1) {
    asm volatile(
        "mma.sync.aligned.m16n8k16.row.col.f32.bf16.bf16.f32 "
        "{%0,%1,%2,%3},{%4,%5,%6,%7},{%8,%9},{%0,%1,%2,%3};"
        : "+f"(d[0]), "+f"(d[1]), "+f"(d[2]), "+f"(d[3])
        : "r"(a[0]), "r"(a[1]), "r"(a[2]), "r"(a[3]), "r"(b0), "r"(b1));
}
__device__ __forceinline__ void mma_fp16(float* d, const uint32_t* a, uint32_t b0, uint32_t b1) {
    asm volatile(
        "mma.sync.aligned.m16n8k16.row.col.f32.f16.f16.f32 "
        "{%0,%1,%2,%3},{%4,%5,%6,%7},{%8,%9},{%0,%1,%2,%3};"
        : "+f"(d[0]), "+f"(d[1]), "+f"(d[2]), "+f"(d[3])
        : "r"(a[0]), "r"(a[1]), "r"(a[2]), "r"(a[3]), "r"(b0), "r"(b1));
}
#define CP16(dst, src) \
    asm volatile("cp.async.cg.shared.global [%0], [%1], 16;" :: "r"(dst), "l"(src) : "memory")
#define CP_COMMIT() asm volatile("cp.async.commit_group;" ::: "memory")
#define CP_WAITG(n) asm volatile("cp.async.wait_group %0;" :: "n"(n) : "memory")

__device__ __forceinline__ float tanh_fast(float x) {
    float ax = fabsf(x);
    float e  = __expf(2.0f * ax);
    float r  = 1.0f - 2.0f / (e + 1.0f);
    return copysignf(r, x);
}

#define RS 80                      // smem row stride: 64B data + 16B pad
#define KC 32
#define NCH 24                     // 768/32
#define WTB (128 * RS)             // 10240: one 128-row k-chunk tile

// ===========================================================================
// Kernel 1: stats + xhat + seq hi/lo splits
// ===========================================================================
__global__ void __launch_bounds__(256) stats_kernel(const float* __restrict__ seq) {
    __shared__ float warp_s[8];
    __shared__ float stat[2];
    const int r   = blockIdx.x;
    const int tid = threadIdx.x;
    const float* x = seq + (size_t)r * Hn;
    float v0 = x[tid], v1 = x[tid + 256], v2 = x[tid + 512];

    {
        __nv_bfloat16 h0 = __float2bfloat16(v0);
        __nv_bfloat16 h1 = __float2bfloat16(v1);
        __nv_bfloat16 h2 = __float2bfloat16(v2);
        g_seq_hi[(size_t)r*Hn + tid]       = h0;
        g_seq_hi[(size_t)r*Hn + tid + 256] = h1;
        g_seq_hi[(size_t)r*Hn + tid + 512] = h2;
        g_seq_lo[(size_t)r*Hn + tid]       = __float2bfloat16(v0 - __bfloat162float(h0));
        g_seq_lo[(size_t)r*Hn + tid + 256] = __float2bfloat16(v1 - __bfloat162float(h1));
        g_seq_lo[(size_t)r*Hn + tid + 512] = __float2bfloat16(v2 - __bfloat162float(h2));
    }

    float s = v0 + v1 + v2;
    #pragma unroll
    for (int o = 16; o; o >>= 1) s += __shfl_xor_sync(0xffffffffu, s, o);
    if ((tid & 31) == 0) warp_s[tid >> 5] = s;
    __syncthreads();
    if (tid == 0) {
        float t = 0.f;
        #pragma unroll
        for (int i = 0; i < 8; i++) t += warp_s[i];
        stat[0] = t * (1.0f / (float)Hn);
    }
    __syncthreads();
    const float mean = stat[0];
    float d0 = v0 - mean, d1 = v1 - mean, d2 = v2 - mean;
    float s2 = d0*d0 + d1*d1 + d2*d2;
    #pragma unroll
    for (int o = 16; o; o >>= 1) s2 += __shfl_xor_sync(0xffffffffu, s2, o);
    if ((tid & 31) == 0) warp_s[tid >> 5] = s2;
    __syncthreads();
    if (tid == 0) {
        float t = 0.f;
        #pragma unroll
        for (int i = 0; i < 8; i++) t += warp_s[i];
        float var = t * (1.0f / (float)Hn);
        float d = var + 1e-12f;
        stat[1] = 1.0f / (d * d);                 // ref quirk: (var+eps)^2, no sqrt
    }
    __syncthreads();
    const float inv = stat[1];
    float* xo = g_xhat + (size_t)r * Hn;
    xo[tid]       = d0 * inv;
    xo[tid + 256] = d1 * inv;
    xo[tid + 512] = d2 * inv;
}

// ===========================================================================
// Kernel 1b: cln weight bf16 splits   Kernel 1c: projection weights -> fp16 ^T
// ===========================================================================
__global__ void __launch_bounds__(256) wsplit_cln_kernel(
    const float* __restrict__ w_gamma, const float* __restrict__ w_beta)
{
    int idx = blockIdx.x * 256 + threadIdx.x;
    if (idx >= 2 * Hn * Hn) return;
    int z = idx / (Hn * Hn);
    int e = idx - z * (Hn * Hn);
    float v = (z ? w_beta : w_gamma)[e];
    __nv_bfloat16 hi = __float2bfloat16(v);
    __nv_bfloat16 lo = __float2bfloat16(v - __bfloat162float(hi));
    if (z) { g_Wb_hi[e] = hi; g_Wb_lo[e] = lo; }
    else   { g_Wg_hi[e] = hi; g_Wg_lo[e] = lo; }
}

__global__ void __launch_bounds__(256) wproj_half_kernel(
    const float* __restrict__ w_ent,
    const float* __restrict__ w_head,
    const float* __restrict__ w_tail)
{
    int idx = blockIdx.x * 256 + threadIdx.x;
    if (idx >= 3 * Mn * Hn) return;
    int k  = idx / (Mn * Hn);
    int rm = idx - k * (Mn * Hn);
    int m  = rm / Hn;
    int h  = rm - m * Hn;
    const float* W = (k == 0) ? w_ent : (k == 1) ? w_head : w_tail;
    g_Wth[idx] = __float2half(W[(size_t)h * Mn + m]);   // transpose [h][m] -> [m][h]
}

// ===========================================================================
// Kernel 2: cln NT GEMM via bf16x3 HMMA -> g_gc / g_bc  (accurate path)
// ===========================================================================
#define CLN_ATB 10240
#define CLN_WOFF (4 * CLN_ATB)
#define CLN_BIAS (CLN_WOFF + 4 * WTB)
#define CLN_SMEM (CLN_BIAS + 512 + 16)

__global__ void __launch_bounds__(256, 2) cln_hmma_kernel(
    const float* __restrict__ gamma, const float* __restrict__ beta)
{
    extern __shared__ __align__(128) char dsm[];
    const uint32_t sB = smem_u32(dsm);
    float* biasS = (float*)(dsm + CLN_BIAS);

    const int z  = blockIdx.z;
    const __nv_bfloat16* Wh_g = z ? g_Wb_hi : g_Wg_hi;
    const __nv_bfloat16* Wl_g = z ? g_Wb_lo : g_Wg_lo;
    const float* bias = z ? beta : gamma;
    float* dst        = z ? g_bc : g_gc;

    const int r0 = blockIdx.x * 128;
    const int c0 = blockIdx.y * 128;
    const int tid  = threadIdx.x;
    const int wid  = tid >> 5;
    const int lane = tid & 31;
    const int g    = lane >> 2;
    const int tg   = lane & 3;
    const int wm   = wid >> 1, wn = wid & 1;

    if (tid < 128) biasS[tid] = bias[c0 + tid];

    float acc[2][8][4];
    #pragma unroll
    for (int mt = 0; mt < 2; mt++)
        #pragma unroll
        for (int nt = 0; nt < 8; nt++)
            #pragma unroll
            for (int r = 0; r < 4; r++) acc[mt][nt][r] = 0.f;

    const int lrow = tid >> 1, fhalf = tid & 1;
    const uint32_t dro = (uint32_t)(lrow * RS + fhalf * 32);

    auto fill = [&](int c, int s) {
        const int kc = c * KC;
        size_t asrc = (size_t)(r0 + lrow) * Hn + kc + fhalf * 16;
        size_t wsrc = (size_t)(c0 + lrow) * Hn + kc + fhalf * 16;
        uint32_t ad = sB + s * (2 * CLN_ATB) + dro;
        uint32_t wd = sB + CLN_WOFF + s * (2 * WTB) + dro;
        CP16(ad,                  (const char*)(g_seq_hi + asrc));
        CP16(ad + 16,             (const char*)(g_seq_hi + asrc + 8));
        CP16(ad + CLN_ATB,        (const char*)(g_seq_lo + asrc));
        CP16(ad + CLN_ATB + 16,   (const char*)(g_seq_lo + asrc + 8));
        CP16(wd,                  (const char*)(Wh_g + wsrc));
        CP16(wd + 16,             (const char*)(Wh_g + wsrc + 8));
        CP16(wd + WTB,            (const char*)(Wl_g + wsrc));
        CP16(wd + WTB + 16,       (const char*)(Wl_g + wsrc + 8));
        CP_COMMIT();
    };

    const uint32_t loff = (uint32_t)(((lane & 7) + ((lane >> 3) & 1) * 8) * RS + (lane >> 4) * 16);

    fill(0, 0);
    for (int c = 0; c < NCH; ++c) {
        const int s = c & 1;
        if (c + 1 < NCH) { __syncthreads(); fill(c + 1, s ^ 1); CP_WAITG(1); }
        else             { CP_WAITG(0); }
        __syncthreads();

        const uint32_t aH = sB + s * (2 * CLN_ATB);
        const uint32_t aL = aH + CLN_ATB;
        const uint32_t wH = sB + CLN_WOFF + s * (2 * WTB);
        const uint32_t wL = wH + WTB;

        #pragma unroll
        for (int ks = 0; ks < 2; ks++) {
            const uint32_t ko = ks * 32 + loff;
            uint32_t Ah[2][4], Al[2][4];
            #pragma unroll
            for (int mt = 0; mt < 2; mt++) {
                uint32_t ab = (uint32_t)((wm * 32 + mt * 16) * RS) + ko;
                ldmx4(Ah[mt][0], Ah[mt][1], Ah[mt][2], Ah[mt][3], aH + ab);
                ldmx4(Al[mt][0], Al[mt][1], Al[mt][2], Al[mt][3], aL + ab);
            }
            #pragma unroll
            for (int ntp = 0; ntp < 4; ntp++) {
                uint32_t wb = (uint32_t)((wn * 64 + ntp * 16) * RS) + ko;
                uint32_t h0, h1, h2, h3, l0, l1, l2, l3;
                ldmx4(h0, h1, h2, h3, wH + wb);
                ldmx4(l0, l1, l2, l3, wL + wb);
                #pragma unroll
                for (int mt = 0; mt < 2; mt++) {
                    mma_bf(acc[mt][2*ntp],   Ah[mt], h0, h2);
                    mma_bf(acc[mt][2*ntp],   Ah[mt], l0, l2);
                    mma_bf(acc[mt][2*ntp],   Al[mt], h0, h2);
                    mma_bf(acc[mt][2*ntp+1], Ah[mt], h1, h3);
                    mma_bf(acc[mt][2*ntp+1], Ah[mt], l1, l3);
                    mma_bf(acc[mt][2*ntp+1], Al[mt], h1, h3);
                }
            }
        }
    }

    #pragma unroll
    for (int mt = 0; mt < 2; mt++) {
        const int row = r0 + wm * 32 + mt * 16 + g;
        #pragma unroll
        for (int nt = 0; nt < 8; nt++) {
            const int cc = wn * 64 + nt * 8 + tg * 2;
            const float b0v = biasS[cc], b1v = biasS[cc + 1];
            const float* d = acc[mt][nt];
            *(float2*)(dst + (size_t)row * Hn + c0 + cc) =
                make_float2(d[0] + b0v, d[1] + b1v);
            *(float2*)(dst + (size_t)(row + 8) * Hn + c0 + cc) =
                make_float2(d[2] + b0v, d[3] + b1v);
        }
    }
}

// ===========================================================================
// Kernel 3: cmat NN GEMM (fp32) -> g_Cmat, 16-row tiles, grid (64,3)
// ===========================================================================
__global__ void __launch_bounds__(256) cmat_gemm_kernel(
    const float* __restrict__ w_ent,  const float* __restrict__ b_ent,
    const float* __restrict__ w_head, const float* __restrict__ b_head,
    const float* __restrict__ w_tail, const float* __restrict__ b_tail)
{
    __shared__ float Ash[32][17];
    __shared__ float Bsh[32][132];
    const int k = blockIdx.y;
    const float* W    = (k == 0) ? w_ent : (k == 1) ? w_head : w_tail;
    const float* bias = (k == 0) ? b_ent : (k == 1) ? b_head : b_tail;
    const int r0 = blockIdx.x * 16;
    const int tid = threadIdx.x;
    const int tx = tid & 15, ty = tid >> 4;
    const int arow = tid & 15, akq = tid >> 4;
    const int bk = tid >> 4, bm0 = (tid & 15) * 8;

    float acc[8];
    #pragma unroll
    for (int v = 0; v < 8; v++) acc[v] = 0.f;

    for (int k0 = 0; k0 < Hn; k0 += 32) {
        float2 a = *(const float2*)(g_bc + (size_t)(r0 + arow) * Hn + k0 + 2 * akq);
        Ash[2*akq][arow]   = a.x;
        Ash[2*akq+1][arow] = a.y;
        const float4* bp0 = (const float4*)(W + (size_t)(k0 + bk) * Mn + bm0);
        const float4* bp1 = (const float4*)(W + (size_t)(k0 + bk + 16) * Mn + bm0);
        *(float4*)&Bsh[bk][bm0]        = bp0[0];
        *(float4*)&Bsh[bk][bm0 + 4]    = bp0[1];
        *(float4*)&Bsh[bk+16][bm0]     = bp1[0];
        *(float4*)&Bsh[bk+16][bm0 + 4] = bp1[1];
        __syncthreads();
        #pragma unroll
        for (int kk = 0; kk < 32; kk++) {
            float a0 = Ash[kk][ty];
            #pragma unroll
            for (int v = 0; v < 8; v++) acc[v] += a0 * Bsh[kk][tx + 16*v];
        }
        __syncthreads();
    }
    {
        int rr = r0 + ty;
        #pragma unroll
        for (int v = 0; v < 8; v++) {
            int cc = tx + 16*v;
            g_Cmat[((size_t)k * (Bn*Sn) + rr) * Mn + cc] = acc[v] + bias[cc];
        }
    }
}

// ===========================================================================
// Kernel 4: pair GEMM, head-split, SINGLE-PASS fp16 HMMA, triangular-trimmed.
//   One CTA per (b, i, head). Rows j in [J0,128), cols m in [0,128).
//   x prefetched to regs 1 chunk ahead; W cp.async 2 stages ahead.
// ===========================================================================
template<int J0, int MWARP, int NWARP, int MT, int NTP>
__global__ void __launch_bounds__(256, 2) pair_f16_kernel(float* __restrict__ out) {
    constexpr int R    = 128 - J0;
    constexpr int ATB  = R * RS;
    constexpr int WOFF = 2 * ATB;
    constexpr int GOFF = WOFF + 2 * WTB;
    constexpr int COFF = GOFF + Hn * 4;

    extern __shared__ __align__(128) char dsm[];
    const uint32_t sB = smem_u32(dsm);
    float* gcs = (float*)(dsm + GOFF);
    float* cmS = (float*)(dsm + COFF);

    const int tid  = threadIdx.x;
    const int wid  = tid >> 5;
    const int lane = tid & 31;
    const int g    = lane >> 2;
    const int tg   = lane & 3;
    const int wn   = wid % NWARP;
    const int wm   = wid / NWARP;
    const int i    = J0 + (blockIdx.x & 31);
    const int b    = blockIdx.x >> 5;
    const int head = blockIdx.y;

    {
        const float* gsrc = g_gc + (size_t)(b * Sn + i) * Hn;
        for (int t = tid; t < Hn; t += 256) gcs[t] = gsrc[t];
        if (tid < 128)
            cmS[tid] = g_Cmat[((size_t)head * (Bn*Sn) + b * Sn + i) * Mn + tid];
    }
    __syncthreads();

    float acc[MT][2*NTP][4];
    #pragma unroll
    for (int mt = 0; mt < MT; mt++)
        #pragma unroll
        for (int nt = 0; nt < 2*NTP; nt++)
            #pragma unroll
            for (int r = 0; r < 4; r++) acc[mt][nt][r] = 0.f;

    const int lrow = tid >> 1, fhalf = tid & 1;
    const uint32_t dro = (uint32_t)(lrow * RS + fhalf * 32);
    const float* xrow = g_xhat + (size_t)(b * Sn + J0 + lrow) * Hn;
    const bool afill = (tid < 2 * R);

    // W producer: 32B per thread per chunk (fp16, hi only)
    auto cpW = [&](int c, int s) {
        size_t wsrc = (size_t)(head * Mn + lrow) * Hn + c * KC + fhalf * 16;
        uint32_t wd = sB + WOFF + s * WTB + dro;
        CP16(wd,      (const char*)(g_Wth + wsrc));
        CP16(wd + 16, (const char*)(g_Wth + wsrc + 8));
        CP_COMMIT();
    };

    float4 xr0, xr1, xr2, xr3;
    auto ldx = [&](int c) {
        if (afill) {
            const float4* xp = (const float4*)(xrow + c * KC + fhalf * 16);
            xr0 = xp[0]; xr1 = xp[1]; xr2 = xp[2]; xr3 = xp[3];
        }
    };

    cpW(0, 0);
    cpW(1, 1);
    ldx(0);

    const uint32_t loff = (uint32_t)(((lane & 7) + ((lane >> 3) & 1) * 8) * RS + (lane >> 4) * 16);

    for (int c = 0; c < NCH; ++c) {
        const int s = c & 1;

        // build + store A(s) from prefetched regs (xhat * gc -> fp16)
        if (afill) {
            const float4* gp = (const float4*)(gcs + c * KC + fhalf * 16);
            float4 g0 = gp[0], g1 = gp[1], g2 = gp[2], g3 = gp[3];
            __half2 h[8];
            h[0] = __floats2half2_rn(xr0.x * g0.x, xr0.y * g0.y);
            h[1] = __floats2half2_rn(xr0.z * g0.z, xr0.w * g0.w);
            h[2] = __floats2half2_rn(xr1.x * g1.x, xr1.y * g1.y);
            h[3] = __floats2half2_rn(xr1.z * g1.z, xr1.w * g1.w);
            h[4] = __floats2half2_rn(xr2.x * g2.x, xr2.y * g2.y);
            h[5] = __floats2half2_rn(xr2.z * g2.z, xr2.w * g2.w);
            h[6] = __floats2half2_rn(xr3.x * g3.x, xr3.y * g3.y);
            h[7] = __floats2half2_rn(xr3.z * g3.z, xr3.w * g3.w);
            char* ab = dsm + s * ATB;
            *(uint4*)(ab + dro)      = *(uint4*)&h[0];
            *(uint4*)(ab + dro + 16) = *(uint4*)&h[4];
        }
        if (c + 1 < NCH) ldx(c + 1);          // prefetch next x chunk

        if (c + 1 < NCH) { CP_WAITG(1); }     // W(c) arrived
        else             { CP_WAITG(0); }
        __syncthreads();

        const uint32_t aB = sB + s * ATB;
        const uint32_t wB = sB + WOFF + s * WTB;

        #pragma unroll
        for (int ks = 0; ks < 2; ks++) {
            const uint32_t ko = ks * 32 + loff;
            uint32_t Ah[MT][4];
            #pragma unroll
            for (int mt = 0; mt < MT; mt++) {
                uint32_t ab = (uint32_t)((wm * MT * 16 + mt * 16) * RS) + ko;
                ldmx4(Ah[mt][0], Ah[mt][1], Ah[mt][2], Ah[mt][3], aB + ab);
            }
            #pragma unroll
            for (int ntp = 0; ntp < NTP; ntp++) {
                uint32_t wb = (uint32_t)((wn * NTP * 16 + ntp * 16) * RS) + ko;
                uint32_t h0, h1, h2, h3;
                ldmx4(h0, h1, h2, h3, wB + wb);
                #pragma unroll
                for (int mt = 0; mt < MT; mt++) {
                    mma_fp16(acc[mt][2*ntp],   Ah[mt], h0, h2);
                    mma_fp16(acc[mt][2*ntp+1], Ah[mt], h1, h3);
                }
            }
        }
        __syncthreads();                      // all reads of stage s done
        if (c + 2 < NCH) cpW(c + 2, s);       // refill W stage s
    }

    // epilogue
    const int offi = i * Sn - (i * (i - 1)) / 2;
    const size_t hb = (size_t)(head * Bn + b) * Pn;
    #pragma unroll
    for (int mt = 0; mt < MT; mt++) {
        const int j0r = J0 + wm * MT * 16 + mt * 16 + g;
        #pragma unroll
        for (int nt = 0; nt < 2*NTP; nt++) {
            const int m = wn * NTP * 16 + nt * 8 + tg * 2;
            const float cm0 = cmS[m], cm1 = cmS[m + 1];
            const float* d = acc[mt][nt];
            if (j0r >= i) {
                *(float2*)(out + (hb + (size_t)(offi - i + j0r)) * Mn + m) =
                    make_float2(tanh_fast(d[0] + cm0), tanh_fast(d[1] + cm1));
            }
            const int j1r = j0r + 8;
            if (j1r >= i) {
                *(float2*)(out + (hb + (size_t)(offi - i + j1r)) * Mn + m) =
                    make_float2(tanh_fast(d[2] + cm0), tanh_fast(d[3] + cm1));
            }
        }
    }
}

static inline int pair_smem(int R) { return 2 * R * RS + 2 * WTB + Hn * 4 + 512 + 16; }

// ===========================================================================
extern "C" void kernel_launch(void* const* d_in, const int* in_sizes, int n_in,
                              void* d_out, int out_size) {
    (void)in_sizes; (void)n_in; (void)out_size;
    const float* seq     = (const float*)d_in[0];
    const float* gamma   = (const float*)d_in[1];
    const float* beta    = (const float*)d_in[2];
    const float* w_beta  = (const float*)d_in[3];
    const float* w_gamma = (const float*)d_in[4];
    const float* w_ent   = (const float*)d_in[5];
    const float* b_ent   = (const float*)d_in[6];
    const float* w_head  = (const float*)d_in[7];
    const float* b_head  = (const float*)d_in[8];
    const float* w_tail  = (const float*)d_in[9];
    const float* b_tail  = (const float*)d_in[10];
    float* out = (float*)d_out;

    cudaFuncSetAttribute(cln_hmma_kernel,
                         cudaFuncAttributeMaxDynamicSharedMemorySize, CLN_SMEM);
    cudaFuncSetAttribute(pair_f16_kernel<0,4,2,2,4>,
                         cudaFuncAttributeMaxDynamicSharedMemorySize, pair_smem(128));
    cudaFuncSetAttribute(pair_f16_kernel<32,2,4,3,2>,
                         cudaFuncAttributeMaxDynamicSharedMemorySize, pair_smem(96));
    cudaFuncSetAttribute(pair_f16_kernel<64,2,4,2,2>,
                         cudaFuncAttributeMaxDynamicSharedMemorySize, pair_smem(64));
    cudaFuncSetAttribute(pair_f16_kernel<96,1,8,2,1>,
                         cudaFuncAttributeMaxDynamicSharedMemorySize, pair_smem(32));

    stats_kernel<<<Bn * Sn, 256>>>(seq);
    wsplit_cln_kernel<<<(2 * Hn * Hn + 255) / 256, 256>>>(w_gamma, w_beta);
    wproj_half_kernel<<<(3 * Mn * Hn + 255) / 256, 256>>>(w_ent, w_head, w_tail);
    cln_hmma_kernel<<<dim3(8, 6, 2), 256, CLN_SMEM>>>(gamma, beta);
    cmat_gemm_kernel<<<dim3(64, 3), 256>>>(w_ent, b_ent, w_head, b_head, w_tail, b_tail);

    pair_f16_kernel<0,4,2,2,4><<<dim3(256, 3), 256, pair_smem(128)>>>(out);
    pair_f16_kernel<32,2,4,3,2><<<dim3(256, 3), 256, pair_smem(96)>>>(out);
    pair_f16_kernel<64,2,4,2,2><<<dim3(256, 3), 256, pair_smem(64)>>>(out);
    pair_f16_kernel<96,1,8,2,1><<<dim3(256, 3), 256, pair_smem(32)>>>(out);
}

// round 9
// speedup vs baseline: 4.4275x; 1.1246x over previous
#include <cuda_runtime.h>
#include <cuda_bf16.h>
#include <cuda_fp16.h>
#include <math.h>
#include <stdint.h>

// Problem constants: B=8, S=128, H=768, M=128, P = S(S+1)/2 = 8256
#define Bn 8
#define Sn 128
#define Hn 768
#define Mn 128
#define Pn 8256

// Scratch (__device__ globals; allocation-free rule)
__device__ float g_xhat[Bn*Sn*Hn];                         // (x-mean)/(var+eps)^2
__device__ float g_gc  [Bn*Sn*Hn];                         // seq @ w_gamma^T + gamma
__device__ float g_bc  [Bn*Sn*Hn];                         // seq @ w_beta^T  + beta
__device__ float g_Cmat[3*Bn*Sn*Mn];                       // bc @ W_k + bias_k
__device__ __align__(16) __half g_Wth[3*Mn*Hn];            // W_k^T fp16 [k][m][h]
__device__ __align__(16) __nv_bfloat16 g_seq_hi[Bn*Sn*Hn]; // seq split hi (cln)
__device__ __align__(16) __nv_bfloat16 g_seq_lo[Bn*Sn*Hn];
__device__ __align__(16) __nv_bfloat16 g_Wg_hi[Hn*Hn];     // w_gamma [o][h] hi
__device__ __align__(16) __nv_bfloat16 g_Wg_lo[Hn*Hn];
__device__ __align__(16) __nv_bfloat16 g_Wb_hi[Hn*Hn];     // w_beta  [o][h] hi
__device__ __align__(16) __nv_bfloat16 g_Wb_lo[Hn*Hn];

// ---------------------------------------------------------------------------
__device__ __forceinline__ uint32_t smem_u32(const void* p) {
    uint32_t a;
    asm("{ .reg .u64 t; cvta.to.shared.u64 t, %1; cvt.u32.u64 %0, t; }" : "=r"(a) : "l"(p));
    return a;
}
__device__ __forceinline__ void ldmx4(uint32_t& r0, uint32_t& r1, uint32_t& r2, uint32_t& r3,
                                      uint32_t a) {
    asm volatile("ldmatrix.sync.aligned.m8n8.x4.shared.b16 {%0,%1,%2,%3}, [%4];"
                 : "=r"(r0), "=r"(r1), "=r"(r2), "=r"(r3) : "r"(a));
}
__device__ __forceinline__ void mma_bf(float* d, const uint32_t* a, uint32_t b0, uint32_t b1) {
    asm volatile(
        "mma.sync.aligned.m16n8k16.row.col.f32.bf16.bf16.f32 "
        "{%0,%1,%2,%3},{%4,%5,%6,%7},{%8,%9},{%0,%1,%2,%3};"
        : "+f"(d[0]), "+f"(d[1]), "+f"(d[2]), "+f"(d[3])
        : "r"(a[0]), "r"(a[1]), "r"(a[2]), "r"(a[3]), "r"(b0), "r"(b1));
}
__device__ __forceinline__ void mma_fp16(float* d, const uint32_t* a, uint32_t b0, uint32_t b1) {
    asm volatile(
        "mma.sync.aligned.m16n8k16.row.col.f32.f16.f16.f32 "
        "{%0,%1,%2,%3},{%4,%5,%6,%7},{%8,%9},{%0,%1,%2,%3};"
        : "+f"(d[0]), "+f"(d[1]), "+f"(d[2]), "+f"(d[3])
        : "r"(a[0]), "r"(a[1]), "r"(a[2]), "r"(a[3]), "r"(b0), "r"(b1));
}
#define CP16(dst, src) \
    asm volatile("cp.async.cg.shared.global [%0], [%1], 16;" :: "r"(dst), "l"(src) : "memory")
#define CP_COMMIT() asm volatile("cp.async.commit_group;" ::: "memory")
#define CP_WAITG(n) asm volatile("cp.async.wait_group %0;" :: "n"(n) : "memory")

__device__ __forceinline__ float tanh_fast(float x) {
    float ax = fabsf(x);
    float e  = __expf(2.0f * ax);
    float r  = 1.0f - 2.0f / (e + 1.0f);
    return copysignf(r, x);
}

#define RS 80                      // smem row stride: 64B data + 16B pad
#define KC 32
#define NCH 24                     // 768/32
#define WTB (128 * RS)             // 10240: 128-row k-chunk tile

// ===========================================================================
// Kernel 1: stats + xhat + seq hi/lo splits
// ===========================================================================
__global__ void __launch_bounds__(256) stats_kernel(const float* __restrict__ seq) {
    __shared__ float warp_s[8];
    __shared__ float stat[2];
    const int r   = blockIdx.x;
    const int tid = threadIdx.x;
    const float* x = seq + (size_t)r * Hn;
    float v0 = x[tid], v1 = x[tid + 256], v2 = x[tid + 512];

    {
        __nv_bfloat16 h0 = __float2bfloat16(v0);
        __nv_bfloat16 h1 = __float2bfloat16(v1);
        __nv_bfloat16 h2 = __float2bfloat16(v2);
        g_seq_hi[(size_t)r*Hn + tid]       = h0;
        g_seq_hi[(size_t)r*Hn + tid + 256] = h1;
        g_seq_hi[(size_t)r*Hn + tid + 512] = h2;
        g_seq_lo[(size_t)r*Hn + tid]       = __float2bfloat16(v0 - __bfloat162float(h0));
        g_seq_lo[(size_t)r*Hn + tid + 256] = __float2bfloat16(v1 - __bfloat162float(h1));
        g_seq_lo[(size_t)r*Hn + tid + 512] = __float2bfloat16(v2 - __bfloat162float(h2));
    }

    float s = v0 + v1 + v2;
    #pragma unroll
    for (int o = 16; o; o >>= 1) s += __shfl_xor_sync(0xffffffffu, s, o);
    if ((tid & 31) == 0) warp_s[tid >> 5] = s;
    __syncthreads();
    if (tid == 0) {
        float t = 0.f;
        #pragma unroll
        for (int i = 0; i < 8; i++) t += warp_s[i];
        stat[0] = t * (1.0f / (float)Hn);
    }
    __syncthreads();
    const float mean = stat[0];
    float d0 = v0 - mean, d1 = v1 - mean, d2 = v2 - mean;
    float s2 = d0*d0 + d1*d1 + d2*d2;
    #pragma unroll
    for (int o = 16; o; o >>= 1) s2 += __shfl_xor_sync(0xffffffffu, s2, o);
    if ((tid & 31) == 0) warp_s[tid >> 5] = s2;
    __syncthreads();
    if (tid == 0) {
        float t = 0.f;
        #pragma unroll
        for (int i = 0; i < 8; i++) t += warp_s[i];
        float var = t * (1.0f / (float)Hn);
        float d = var + 1e-12f;
        stat[1] = 1.0f / (d * d);                 // ref quirk: (var+eps)^2, no sqrt
    }
    __syncthreads();
    const float inv = stat[1];
    float* xo = g_xhat + (size_t)r * Hn;
    xo[tid]       = d0 * inv;
    xo[tid + 256] = d1 * inv;
    xo[tid + 512] = d2 * inv;
}

// ===========================================================================
// Kernel 1b: cln weight bf16 splits   Kernel 1c: projection weights -> fp16 ^T
// ===========================================================================
__global__ void __launch_bounds__(256) wsplit_cln_kernel(
    const float* __restrict__ w_gamma, const float* __restrict__ w_beta)
{
    int idx = blockIdx.x * 256 + threadIdx.x;
    if (idx >= 2 * Hn * Hn) return;
    int z = idx / (Hn * Hn);
    int e = idx - z * (Hn * Hn);
    float v = (z ? w_beta : w_gamma)[e];
    __nv_bfloat16 hi = __float2bfloat16(v);
    __nv_bfloat16 lo = __float2bfloat16(v - __bfloat162float(hi));
    if (z) { g_Wb_hi[e] = hi; g_Wb_lo[e] = lo; }
    else   { g_Wg_hi[e] = hi; g_Wg_lo[e] = lo; }
}

__global__ void __launch_bounds__(256) wproj_half_kernel(
    const float* __restrict__ w_ent,
    const float* __restrict__ w_head,
    const float* __restrict__ w_tail)
{
    int idx = blockIdx.x * 256 + threadIdx.x;
    if (idx >= 3 * Mn * Hn) return;
    int k  = idx / (Mn * Hn);
    int rm = idx - k * (Mn * Hn);
    int m  = rm / Hn;
    int h  = rm - m * Hn;
    const float* W = (k == 0) ? w_ent : (k == 1) ? w_head : w_tail;
    g_Wth[idx] = __float2half(W[(size_t)h * Mn + m]);   // transpose [h][m] -> [m][h]
}

// ===========================================================================
// Kernel 2: cln NT GEMM via bf16x3 HMMA -> g_gc / g_bc
//   64x64 tiles, grid (16, 12, 2) = 384 CTAs; acc=16 regs, 3 CTAs/SM.
// ===========================================================================
#define CL_ATB 5120                       // 64 rows * 80
#define CL_WOFF (4 * CL_ATB)              // 20480
#define CL_WTB 5120
#define CL_BIAS (CL_WOFF + 4 * CL_WTB)    // 40960
#define CL_SMEM (CL_BIAS + 256 + 16)

__global__ void __launch_bounds__(256, 3) cln_hmma_kernel(
    const float* __restrict__ gamma, const float* __restrict__ beta)
{
    extern __shared__ __align__(128) char dsm[];
    const uint32_t sB = smem_u32(dsm);
    float* biasS = (float*)(dsm + CL_BIAS);

    const int z  = blockIdx.z;
    const __nv_bfloat16* Wh_g = z ? g_Wb_hi : g_Wg_hi;
    const __nv_bfloat16* Wl_g = z ? g_Wb_lo : g_Wg_lo;
    const float* bias = z ? beta : gamma;
    float* dst        = z ? g_bc : g_gc;

    const int r0 = blockIdx.x * 64;
    const int c0 = blockIdx.y * 64;
    const int tid  = threadIdx.x;
    const int wid  = tid >> 5;
    const int lane = tid & 31;
    const int g    = lane >> 2;
    const int tg   = lane & 3;
    const int wm   = wid >> 1, wn = wid & 1;

    if (tid < 64) biasS[tid] = bias[c0 + tid];

    float acc[4][4];
    #pragma unroll
    for (int nt = 0; nt < 4; nt++)
        #pragma unroll
        for (int r = 0; r < 4; r++) acc[nt][r] = 0.f;

    // fill: tid<128 -> A rows, tid>=128 -> W rows
    const int lrow  = (tid & 127) >> 1;
    const int fhalf = tid & 1;
    const uint32_t dro = (uint32_t)(lrow * RS + fhalf * 32);
    const bool isA = (tid < 128);

    auto fill = [&](int c, int s) {
        const int kc = c * KC;
        if (isA) {
            size_t asrc = (size_t)(r0 + lrow) * Hn + kc + fhalf * 16;
            uint32_t ad = sB + s * (2 * CL_ATB) + dro;
            CP16(ad,                (const char*)(g_seq_hi + asrc));
            CP16(ad + 16,           (const char*)(g_seq_hi + asrc + 8));
            CP16(ad + CL_ATB,       (const char*)(g_seq_lo + asrc));
            CP16(ad + CL_ATB + 16,  (const char*)(g_seq_lo + asrc + 8));
        } else {
            size_t wsrc = (size_t)(c0 + lrow) * Hn + kc + fhalf * 16;
            uint32_t wd = sB + CL_WOFF + s * (2 * CL_WTB) + dro;
            CP16(wd,                (const char*)(Wh_g + wsrc));
            CP16(wd + 16,           (const char*)(Wh_g + wsrc + 8));
            CP16(wd + CL_WTB,       (const char*)(Wl_g + wsrc));
            CP16(wd + CL_WTB + 16,  (const char*)(Wl_g + wsrc + 8));
        }
        CP_COMMIT();
    };

    const uint32_t loff = (uint32_t)(((lane & 7) + ((lane >> 3) & 1) * 8) * RS + (lane >> 4) * 16);

    fill(0, 0);
    for (int c = 0; c < NCH; ++c) {
        const int s = c & 1;
        if (c + 1 < NCH) { __syncthreads(); fill(c + 1, s ^ 1); CP_WAITG(1); }
        else             { CP_WAITG(0); }
        __syncthreads();

        const uint32_t aH = sB + s * (2 * CL_ATB);
        const uint32_t aL = aH + CL_ATB;
        const uint32_t wH = sB + CL_WOFF + s * (2 * CL_WTB);
        const uint32_t wL = wH + CL_WTB;

        #pragma unroll
        for (int ks = 0; ks < 2; ks++) {
            const uint32_t ko = ks * 32 + loff;
            uint32_t Ah[4], Al[4];
            uint32_t ab = (uint32_t)((wm * 16) * RS) + ko;
            ldmx4(Ah[0], Ah[1], Ah[2], Ah[3], aH + ab);
            ldmx4(Al[0], Al[1], Al[2], Al[3], aL + ab);
            #pragma unroll
            for (int ntp = 0; ntp < 2; ntp++) {
                uint32_t wb = (uint32_t)((wn * 32 + ntp * 16) * RS) + ko;
                uint32_t h0, h1, h2, h3, l0, l1, l2, l3;
                ldmx4(h0, h1, h2, h3, wH + wb);
                ldmx4(l0, l1, l2, l3, wL + wb);
                mma_bf(acc[2*ntp],   Ah, h0, h2);
                mma_bf(acc[2*ntp],   Ah, l0, l2);
                mma_bf(acc[2*ntp],   Al, h0, h2);
                mma_bf(acc[2*ntp+1], Ah, h1, h3);
                mma_bf(acc[2*ntp+1], Ah, l1, l3);
                mma_bf(acc[2*ntp+1], Al, h1, h3);
            }
        }
    }

    {
        const int row = r0 + wm * 16 + g;
        #pragma unroll
        for (int nt = 0; nt < 4; nt++) {
            const int cc = wn * 32 + nt * 8 + tg * 2;
            const float b0v = biasS[cc], b1v = biasS[cc + 1];
            const float* d = acc[nt];
            *(float2*)(dst + (size_t)row * Hn + c0 + cc) =
                make_float2(d[0] + b0v, d[1] + b1v);
            *(float2*)(dst + (size_t)(row + 8) * Hn + c0 + cc) =
                make_float2(d[2] + b0v, d[3] + b1v);
        }
    }
}

// ===========================================================================
// Kernel 3: cmat NN GEMM (fp32) -> g_Cmat, 16-row tiles, K-step 64, grid (64,3)
// ===========================================================================
__global__ void __launch_bounds__(256) cmat_gemm_kernel(
    const float* __restrict__ w_ent,  const float* __restrict__ b_ent,
    const float* __restrict__ w_head, const float* __restrict__ b_head,
    const float* __restrict__ w_tail, const float* __restrict__ b_tail)
{
    __shared__ float Ash[64][17];
    __shared__ float Bsh[64][132];
    const int k = blockIdx.y;
    const float* W    = (k == 0) ? w_ent : (k == 1) ? w_head : w_tail;
    const float* bias = (k == 0) ? b_ent : (k == 1) ? b_head : b_tail;
    const int r0 = blockIdx.x * 16;
    const int tid = threadIdx.x;
    const int tx = tid & 15, ty = tid >> 4;
    const int arow = tid & 15, akq = (tid >> 4) * 4;   // A: float4 at k=akq
    const int bk = tid >> 4, bm0 = (tid & 15) * 8;

    float acc[8];
    #pragma unroll
    for (int v = 0; v < 8; v++) acc[v] = 0.f;

    for (int k0 = 0; k0 < Hn; k0 += 64) {
        float4 a = *(const float4*)(g_bc + (size_t)(r0 + arow) * Hn + k0 + akq);
        Ash[akq+0][arow] = a.x; Ash[akq+1][arow] = a.y;
        Ash[akq+2][arow] = a.z; Ash[akq+3][arow] = a.w;
        #pragma unroll
        for (int rr = 0; rr < 4; rr++) {
            const float4* bp = (const float4*)(W + (size_t)(k0 + bk + rr*16) * Mn + bm0);
            *(float4*)&Bsh[bk + rr*16][bm0]     = bp[0];
            *(float4*)&Bsh[bk + rr*16][bm0 + 4] = bp[1];
        }
        __syncthreads();
        #pragma unroll
        for (int kk = 0; kk < 64; kk++) {
            float a0 = Ash[kk][ty];
            #pragma unroll
            for (int v = 0; v < 8; v++) acc[v] += a0 * Bsh[kk][tx + 16*v];
        }
        __syncthreads();
    }
    {
        int rr = r0 + ty;
        #pragma unroll
        for (int v = 0; v < 8; v++) {
            int cc = tx + 16*v;
            g_Cmat[((size_t)k * (Bn*Sn) + rr) * Mn + cc] = acc[v] + bias[cc];
        }
    }
}

// ===========================================================================
// Kernel 4: MERGED pair GEMM, single-pass fp16 HMMA, runtime triangular trim.
//   One CTA per (b, i, head); R = 128 - (i/32)*32 at runtime.
//   3-stage ring, ONE __syncthreads per chunk; fill runs after MMA issue
//   (writes stage c+2 while chunk c drains). Warp grid 2m x 4n; acc[4][4][4].
// ===========================================================================
#define PAIR_AOFF (3 * WTB)                         // W stages first (fixed)
#define PAIR_SMEM (3 * WTB + 3 * (128 * RS) + Hn * 4 + 512 + 64)

__global__ void __launch_bounds__(256, 2) pair_f16_all(float* __restrict__ out) {
    extern __shared__ __align__(128) char dsm[];
    const uint32_t sB = smem_u32(dsm);

    const int tid  = threadIdx.x;
    const int wid  = tid >> 5;
    const int lane = tid & 31;
    const int g    = lane >> 2;
    const int tg   = lane & 3;
    const int wn   = wid & 3;            // 4 n-warps x 32 cols
    const int wm   = wid >> 2;           // 2 m-warps x R/2 rows
    const int i    = blockIdx.x & 127;
    const int b    = blockIdx.x >> 7;
    const int head = blockIdx.y;

    const int J0  = (i >> 5) << 5;
    const int Rr  = 128 - J0;
    const int MTr = Rr >> 5;             // 1..4
    const int ATB = Rr * RS;
    const int GOFF = PAIR_AOFF + 3 * ATB;
    const int COFF = GOFF + Hn * 4;
    float* gcs = (float*)(dsm + GOFF);
    float* cmS = (float*)(dsm + COFF);

    {
        const float* gsrc = g_gc + (size_t)(b * Sn + i) * Hn;
        for (int t = tid; t < Hn; t += 256) gcs[t] = gsrc[t];
        if (tid < 128)
            cmS[tid] = g_Cmat[((size_t)head * (Bn*Sn) + b * Sn + i) * Mn + tid];
    }
    __syncthreads();

    float acc[4][4][4];
    #pragma unroll
    for (int mt = 0; mt < 4; mt++)
        #pragma unroll
        for (int nt = 0; nt < 4; nt++)
            #pragma unroll
            for (int r = 0; r < 4; r++) acc[mt][nt][r] = 0.f;

    const int lrow = tid >> 1, fhalf = tid & 1;
    const uint32_t dro = (uint32_t)(lrow * RS + fhalf * 32);
    const float* xrow = g_xhat + (size_t)(b * Sn + J0 + lrow) * Hn;
    const bool afill = (tid < 2 * Rr);

    float4 xr0, xr1, xr2, xr3;
    auto ldx = [&](int c) {
        if (afill) {
            const float4* xp = (const float4*)(xrow + c * KC + fhalf * 16);
            xr0 = xp[0]; xr1 = xp[1]; xr2 = xp[2]; xr3 = xp[3];
        }
    };
    auto buildA = [&](int c, int s) {
        if (afill) {
            const float4* gp = (const float4*)(gcs + c * KC + fhalf * 16);
            float4 g0 = gp[0], g1 = gp[1], g2 = gp[2], g3 = gp[3];
            __half2 h[8];
            h[0] = __floats2half2_rn(xr0.x * g0.x, xr0.y * g0.y);
            h[1] = __floats2half2_rn(xr0.z * g0.z, xr0.w * g0.w);
            h[2] = __floats2half2_rn(xr1.x * g1.x, xr1.y * g1.y);
            h[3] = __floats2half2_rn(xr1.z * g1.z, xr1.w * g1.w);
            h[4] = __floats2half2_rn(xr2.x * g2.x, xr2.y * g2.y);
            h[5] = __floats2half2_rn(xr2.z * g2.z, xr2.w * g2.w);
            h[6] = __floats2half2_rn(xr3.x * g3.x, xr3.y * g3.y);
            h[7] = __floats2half2_rn(xr3.z * g3.z, xr3.w * g3.w);
            char* ab = dsm + PAIR_AOFF + s * ATB;
            *(uint4*)(ab + dro)      = *(uint4*)&h[0];
            *(uint4*)(ab + dro + 16) = *(uint4*)&h[4];
        }
    };
    auto cpW = [&](int c, int s) {
        size_t wsrc = (size_t)(head * Mn + lrow) * Hn + c * KC + fhalf * 16;
        uint32_t wd = sB + s * WTB + dro;
        CP16(wd,      (const char*)(g_Wth + wsrc));
        CP16(wd + 16, (const char*)(g_Wth + wsrc + 8));
        CP_COMMIT();
    };

    // prologue: stages 0,1
    ldx(0); buildA(0, 0); cpW(0, 0);
    ldx(1); buildA(1, 1); cpW(1, 1);
    ldx(2);

    const uint32_t loff = (uint32_t)(((lane & 7) + ((lane >> 3) & 1) * 8) * RS + (lane >> 4) * 16);
    const uint32_t mrowb = (uint32_t)(wm * MTr * 16);

    for (int c = 0; c < NCH; ++c) {
        const int s = c % 3;
        if (c + 1 < NCH) { CP_WAITG(1); }
        else             { CP_WAITG(0); }
        __syncthreads();     // A(s)/W(s) ready; all reads of stage (c+2)%3 done

        const uint32_t aB = sB + PAIR_AOFF + s * ATB;
        const uint32_t wB = sB + s * WTB;

        #pragma unroll
        for (int ks = 0; ks < 2; ks++) {
            const uint32_t ko = ks * 32 + loff;
            uint32_t Ah[4][4];
            #pragma unroll
            for (int mt = 0; mt < 4; mt++)
                if (mt < MTr) {
                    uint32_t ab = (mrowb + mt * 16) * RS + ko;
                    ldmx4(Ah[mt][0], Ah[mt][1], Ah[mt][2], Ah[mt][3], aB + ab);
                }
            #pragma unroll
            for (int ntp = 0; ntp < 2; ntp++) {
                uint32_t wb = (uint32_t)((wn * 32 + ntp * 16) * RS) + ko;
                uint32_t h0, h1, h2, h3;
                ldmx4(h0, h1, h2, h3, wB + wb);
                #pragma unroll
                for (int mt = 0; mt < 4; mt++)
                    if (mt < MTr) {
                        mma_fp16(acc[mt][2*ntp],   Ah[mt], h0, h2);
                        mma_fp16(acc[mt][2*ntp+1], Ah[mt], h1, h3);
                    }
            }
        }

        if (c + 2 < NCH) {            // fill stage (c+2)%3, off critical path
            const int s2 = (c + 2) % 3;
            buildA(c + 2, s2);
            cpW(c + 2, s2);
            if (c + 3 < NCH) ldx(c + 3);
        }
    }

    // epilogue
    const int offi = i * Sn - (i * (i - 1)) / 2;
    const size_t hb = (size_t)(head * Bn + b) * Pn;
    #pragma unroll
    for (int mt = 0; mt < 4; mt++) {
        if (mt >= MTr) break;
        const int j0r = J0 + wm * MTr * 16 + mt * 16 + g;
        #pragma unroll
        for (int nt = 0; nt < 4; nt++) {
            const int m = wn * 32 + nt * 8 + tg * 2;
            const float cm0 = cmS[m], cm1 = cmS[m + 1];
            const float* d = acc[mt][nt];
            if (j0r >= i) {
                *(float2*)(out + (hb + (size_t)(offi - i + j0r)) * Mn + m) =
                    make_float2(tanh_fast(d[0] + cm0), tanh_fast(d[1] + cm1));
            }
            const int j1r = j0r + 8;
            if (j1r >= i) {
                *(float2*)(out + (hb + (size_t)(offi - i + j1r)) * Mn + m) =
                    make_float2(tanh_fast(d[2] + cm0), tanh_fast(d[3] + cm1));
            }
        }
    }
}

// ===========================================================================
extern "C" void kernel_launch(void* const* d_in, const int* in_sizes, int n_in,
                              void* d_out, int out_size) {
    (void)in_sizes; (void)n_in; (void)out_size;
    const float* seq     = (const float*)d_in[0];
    const float* gamma   = (const float*)d_in[1];
    const float* beta    = (const float*)d_in[2];
    const float* w_beta  = (const float*)d_in[3];
    const float* w_gamma = (const float*)d_in[4];
    const float* w_ent   = (const float*)d_in[5];
    const float* b_ent   = (const float*)d_in[6];
    const float* w_head  = (const float*)d_in[7];
    const float* b_head  = (const float*)d_in[8];
    const float* w_tail  = (const float*)d_in[9];
    const float* b_tail  = (const float*)d_in[10];
    float* out = (float*)d_out;

    cudaFuncSetAttribute(cln_hmma_kernel,
                         cudaFuncAttributeMaxDynamicSharedMemorySize, CL_SMEM);
    cudaFuncSetAttribute(pair_f16_all,
                         cudaFuncAttributeMaxDynamicSharedMemorySize, PAIR_SMEM);

    stats_kernel<<<Bn * Sn, 256>>>(seq);
    wsplit_cln_kernel<<<(2 * Hn * Hn + 255) / 256, 256>>>(w_gamma, w_beta);
    wproj_half_kernel<<<(3 * Mn * Hn + 255) / 256, 256>>>(w_ent, w_head, w_tail);
    cln_hmma_kernel<<<dim3(16, 12, 2), 256, CL_SMEM>>>(gamma, beta);
    cmat_gemm_kernel<<<dim3(64, 3), 256>>>(w_ent, b_ent, w_head, b_head, w_tail, b_tail);
    pair_f16_all<<<dim3(1024, 3), 256, PAIR_SMEM>>>(out);
}